// round 3
// baseline (speedup 1.0000x reference)
#include <cuda_runtime.h>
#include <math.h>

#define N_ALL 8192
#define D_FEAT 256
#define S_SRC 4096
#define C_CLS 65

#define TM 64
#define TN 64
#define TK 32

// Scratch (allocation-free rule: __device__ globals)
__device__ float g_sq[N_ALL];
__device__ float g_row_cl[S_SRC];
__device__ float g_row_ce[S_SRC];
__device__ float g_row_reg[N_ALL];

// ---------------------------------------------------------------------------
// Row squared norms: one warp per row
// ---------------------------------------------------------------------------
__global__ void sq_kernel(const float* __restrict__ F) {
    int warp = (blockIdx.x * blockDim.x + threadIdx.x) >> 5;
    int lane = threadIdx.x & 31;
    if (warp >= N_ALL) return;
    const float4* row = (const float4*)(F + (size_t)warp * D_FEAT);
    float s = 0.f;
    #pragma unroll
    for (int i = 0; i < 2; ++i) {
        float4 v = row[lane + 32 * i];
        s += v.x * v.x + v.y * v.y + v.z * v.z + v.w * v.w;
    }
    #pragma unroll
    for (int o = 16; o; o >>= 1) s += __shfl_xor_sync(0xffffffffu, s, o);
    if (lane == 0) g_sq[warp] = s;
}

// ---------------------------------------------------------------------------
// loss_cl (source rows) + loss_ce (target rows): one warp per row
// ---------------------------------------------------------------------------
__global__ void logit_kernel(const float* __restrict__ L, const int* __restrict__ y) {
    int warp = (blockIdx.x * blockDim.x + threadIdx.x) >> 5;
    int lane = threadIdx.x & 31;
    if (warp >= N_ALL) return;
    const float* row = L + (size_t)warp * C_CLS;

    float l0 = (lane < C_CLS) ? row[lane] : -3.4e38f;
    float l1 = (lane + 32 < C_CLS) ? row[lane + 32] : -3.4e38f;
    float l2 = (lane + 64 < C_CLS) ? row[lane + 64] : -3.4e38f;

    float m = fmaxf(l0, fmaxf(l1, l2));
    #pragma unroll
    for (int o = 16; o; o >>= 1) m = fmaxf(m, __shfl_xor_sync(0xffffffffu, m, o));

    float e0 = (lane < C_CLS) ? expf(l0 - m) : 0.f;
    float e1 = (lane + 32 < C_CLS) ? expf(l1 - m) : 0.f;
    float e2 = (lane + 64 < C_CLS) ? expf(l2 - m) : 0.f;
    float s = e0 + e1 + e2;
    #pragma unroll
    for (int o = 16; o; o >>= 1) s += __shfl_xor_sync(0xffffffffu, s, o);

    if (warp < S_SRC) {
        if (lane == 0) {
            float ly = row[y[warp]];
            g_row_cl[warp] = -(ly - m - logf(s));
        }
    } else {
        float inv = 1.f / s;
        float ent = 0.f;
        if (lane < C_CLS)      { float p = e0 * inv; ent -= p * log2f(fmaxf(p, 1e-8f)); }
        if (lane + 32 < C_CLS) { float p = e1 * inv; ent -= p * log2f(fmaxf(p, 1e-8f)); }
        if (lane + 64 < C_CLS) { float p = e2 * inv; ent -= p * log2f(fmaxf(p, 1e-8f)); }
        #pragma unroll
        for (int o = 16; o; o >>= 1) ent += __shfl_xor_sync(0xffffffffu, ent, o);
        if (lane == 0) g_row_ce[warp - S_SRC] = ent;
    }
}

// ---------------------------------------------------------------------------
// Sorted insert into ascending 5-min list
// ---------------------------------------------------------------------------
__device__ __forceinline__ void ins5(float (&m)[5], float v) {
    if (v < m[4]) {
        if (v < m[3]) { m[4] = m[3];
            if (v < m[2]) { m[3] = m[2];
                if (v < m[1]) { m[2] = m[1];
                    if (v < m[0]) { m[1] = m[0]; m[0] = v; } else m[1] = v;
                } else m[2] = v;
            } else m[3] = v;
        } else m[4] = v;
    }
}

// ---------------------------------------------------------------------------
// Fused pairwise-d2 + per-row 5-min per half + sim/|diff| epilogue.
// Grid: 128 CTAs, one per 64-row tile. Each CTA sweeps all 8192 columns
// (source half, then target half).
// ---------------------------------------------------------------------------
__global__ __launch_bounds__(256) void dist_kernel(const float* __restrict__ F) {
    __shared__ float As[TK][TM + 4];
    __shared__ float Bs[TK][TN + 4];
    __shared__ float Mrg[TM][16 * 5];

    int tid = threadIdx.x;
    int tx = tid & 15;      // column group
    int ty = tid >> 4;      // row group
    int r0 = blockIdx.x * TM;

    float simh0 = 0.f, simh1 = 0.f;

    for (int h = 0; h < 2; ++h) {
        int cbase = h * S_SRC;
        float mn[4][5];
        #pragma unroll
        for (int ii = 0; ii < 4; ++ii)
            #pragma unroll
            for (int q = 0; q < 5; ++q) mn[ii][q] = 3.4e38f;

        for (int jt = 0; jt < S_SRC / TN; ++jt) {
            int c0 = cbase + jt * TN;
            float acc[4][4];
            #pragma unroll
            for (int ii = 0; ii < 4; ++ii)
                #pragma unroll
                for (int jj = 0; jj < 4; ++jj) acc[ii][jj] = 0.f;

            for (int kc = 0; kc < D_FEAT / TK; ++kc) {
                __syncthreads();
                // Load A tile chunk (64 rows x 32 k), transposed into smem
                #pragma unroll
                for (int it = 0; it < 2; ++it) {
                    int f = tid + it * 256;
                    int row = f >> 3;           // 8 float4 per row-chunk
                    int kk = (f & 7) * 4;
                    float4 v = *(const float4*)(F + (size_t)(r0 + row) * D_FEAT + kc * TK + kk);
                    As[kk + 0][row] = v.x; As[kk + 1][row] = v.y;
                    As[kk + 2][row] = v.z; As[kk + 3][row] = v.w;
                }
                // Load B tile chunk (64 cols as feature rows x 32 k)
                #pragma unroll
                for (int it = 0; it < 2; ++it) {
                    int f = tid + it * 256;
                    int row = f >> 3;
                    int kk = (f & 7) * 4;
                    float4 v = *(const float4*)(F + (size_t)(c0 + row) * D_FEAT + kc * TK + kk);
                    Bs[kk + 0][row] = v.x; Bs[kk + 1][row] = v.y;
                    Bs[kk + 2][row] = v.z; Bs[kk + 3][row] = v.w;
                }
                __syncthreads();
                #pragma unroll
                for (int kk = 0; kk < TK; ++kk) {
                    float4 av = *(const float4*)&As[kk][ty * 4];
                    float4 bv = *(const float4*)&Bs[kk][tx * 4];
                    float a[4] = {av.x, av.y, av.z, av.w};
                    float b[4] = {bv.x, bv.y, bv.z, bv.w};
                    #pragma unroll
                    for (int ii = 0; ii < 4; ++ii)
                        #pragma unroll
                        for (int jj = 0; jj < 4; ++jj)
                            acc[ii][jj] += a[ii] * b[jj];
                }
            }
            // Epilogue: d2 = |xi|^2 + |xj|^2 - 2 xi.xj, track 5 smallest
            #pragma unroll
            for (int ii = 0; ii < 4; ++ii) {
                int gi = r0 + ty * 4 + ii;
                float sqa = g_sq[gi];
                #pragma unroll
                for (int jj = 0; jj < 4; ++jj) {
                    int gj = c0 + tx * 4 + jj;
                    float d2 = sqa + g_sq[gj] - 2.f * acc[ii][jj];
                    d2 = (gi == gj) ? 0.f : fmaxf(d2, 0.f);
                    ins5(mn[ii], d2);
                }
            }
        }

        // Merge 16 per-thread partial lists per row
        __syncthreads();
        #pragma unroll
        for (int ii = 0; ii < 4; ++ii)
            #pragma unroll
            for (int q = 0; q < 5; ++q)
                Mrg[ty * 4 + ii][tx * 5 + q] = mn[ii][q];
        __syncthreads();

        if (tid < TM) {
            float s[5];
            #pragma unroll
            for (int q = 0; q < 5; ++q) s[q] = 3.4e38f;
            const float* p = Mrg[tid];
            for (int t = 0; t < 80; ++t) ins5(s, p[t]);

            // diag present iff this half is the intra block for these rows
            bool diag = ((r0 < S_SRC) == (h == 0));
            float dmin2 = diag ? s[1] : s[0];   // intra: min excluding diag (s[0]==0)
            float kth2  = s[4];                 // 5th smallest (incl diag for intra)
            float sim = expf(-sqrtf(dmin2) / (2.f * (sqrtf(kth2) + 1e-8f)));
            if (h == 0) simh0 = sim; else simh1 = sim;
        }
        __syncthreads();
    }

    if (tid < TM) {
        int gi = r0 + tid;
        float intra = (gi < S_SRC) ? simh0 : simh1;
        float inter = (gi < S_SRC) ? simh1 : simh0;
        g_row_reg[gi] = fabsf(intra - inter);
    }
}

// ---------------------------------------------------------------------------
// Deterministic final reduction (fixed order: strided partials + tree)
// ---------------------------------------------------------------------------
__global__ void reduce_kernel(float* __restrict__ out) {
    __shared__ float sh[256];
    int t = threadIdx.x;

    float a = 0.f;
    for (int i = t; i < S_SRC; i += 256) a += g_row_cl[i];
    sh[t] = a; __syncthreads();
    for (int o = 128; o; o >>= 1) { if (t < o) sh[t] += sh[t + o]; __syncthreads(); }
    if (t == 0) out[0] = sh[0] / (float)S_SRC;
    __syncthreads();

    float b = 0.f;
    for (int i = t; i < S_SRC; i += 256) b += g_row_ce[i];
    sh[t] = b; __syncthreads();
    for (int o = 128; o; o >>= 1) { if (t < o) sh[t] += sh[t + o]; __syncthreads(); }
    if (t == 0) out[1] = sh[0] / (float)S_SRC;
    __syncthreads();

    float c = 0.f;
    for (int i = t; i < N_ALL; i += 256) c += g_row_reg[i];
    sh[t] = c; __syncthreads();
    for (int o = 128; o; o >>= 1) { if (t < o) sh[t] += sh[t + o]; __syncthreads(); }
    if (t == 0) out[2] = sh[0] / (float)S_SRC;  // mean over src rows + mean over tgt rows
}

// ---------------------------------------------------------------------------
extern "C" void kernel_launch(void* const* d_in, const int* in_sizes, int n_in,
                              void* d_out, int out_size) {
    const float* F = (const float*)d_in[0];   // Feature_all [8192,256] f32
    const float* L = (const float*)d_in[1];   // logit_all   [8192,65]  f32
    const int*   y = (const int*)d_in[2];     // y_source    [4096]     i32
    float* out = (float*)d_out;               // [loss_cl, loss_ce, loss_reg]

    sq_kernel<<<N_ALL / 8, 256>>>(F);         // 8 warps/block, warp per row
    logit_kernel<<<N_ALL / 8, 256>>>(L, y);
    dist_kernel<<<N_ALL / TM, 256>>>(F);
    reduce_kernel<<<1, 256>>>(out);
}

// round 7
// speedup vs baseline: 3.6460x; 3.6460x over previous
#include <cuda_runtime.h>
#include <cuda_bf16.h>
#include <math.h>
#include <stdint.h>

#define N_ALL 8192
#define D_FEAT 256
#define S_SRC 4096
#define C_CLS 65

// SMEM layout (relative to 1024-aligned base)
#define OFF_SQ 0                 // 4096 f32 = 16384 B (reused as merge buffer later)
#define OFF_B  16384             // 4 stages x 8192 B (hi 4096 + lo 4096)
#define OFF_A  49152             // A hi 65536 + A lo 65536
#define SMEM_BYTES (49152 + 131072)
#define SMEM_ALLOC (SMEM_BYTES + 1024)

// ---------------------------------------------------------------------------
// Scratch (__device__ globals: allocation-free rule)
// ---------------------------------------------------------------------------
__device__ float g_sq[N_ALL];
__device__ float g_row_cl[S_SRC];
__device__ float g_row_ce[S_SRC];
__device__ float g_simh[2 * N_ALL];
__device__ __align__(16) __nv_bfloat16 g_hi[N_ALL * D_FEAT];
__device__ __align__(16) __nv_bfloat16 g_lo[N_ALL * D_FEAT];

// ---------------------------------------------------------------------------
// PTX helpers (baseline PTX only — nothing arch-'a'-gated)
// ---------------------------------------------------------------------------
__device__ __forceinline__ uint32_t smem_to_u32(const void* p) {
    uint32_t a;
    asm("{ .reg .u64 t; cvta.to.shared.u64 t, %1; cvt.u32.u64 %0, t; }" : "=r"(a) : "l"(p));
    return a;
}

#define CP_ASYNC16(DST, SRC) \
    asm volatile("cp.async.cg.shared.global [%0], [%1], 16;" :: "r"(DST), "l"(SRC) : "memory")
#define CP_COMMIT() asm volatile("cp.async.commit_group;" ::: "memory")
#define CP_WAIT2()  asm volatile("cp.async.wait_group 2;" ::: "memory")

#define LDSM4(R, ADDR) \
    asm volatile("ldmatrix.sync.aligned.m8n8.x4.shared.b16 {%0,%1,%2,%3}, [%4];" \
        : "=r"((R)[0]), "=r"((R)[1]), "=r"((R)[2]), "=r"((R)[3]) : "r"(ADDR))

#define MMA16816(D, A, B0, B1) \
    asm volatile("mma.sync.aligned.m16n8k16.row.col.f32.bf16.bf16.f32 " \
        "{%0,%1,%2,%3}, {%4,%5,%6,%7}, {%8,%9}, {%0,%1,%2,%3};" \
        : "+f"((D)[0]), "+f"((D)[1]), "+f"((D)[2]), "+f"((D)[3]) \
        : "r"((A)[0]), "r"((A)[1]), "r"((A)[2]), "r"((A)[3]), "r"(B0), "r"(B1))

// ---------------------------------------------------------------------------
// Fused: row squared norms + f32 -> bf16 hi/lo split images (one warp per row)
// ---------------------------------------------------------------------------
__global__ void prep_kernel(const float* __restrict__ F) {
    int row = (blockIdx.x * blockDim.x + threadIdx.x) >> 5;
    int lane = threadIdx.x & 31;
    if (row >= N_ALL) return;
    const float4* src = (const float4*)(F + (size_t)row * D_FEAT);
    float s = 0.f;
    #pragma unroll
    for (int i = 0; i < 2; ++i) {
        int idx = lane + 32 * i;                 // float4 index within row (0..63)
        float4 v = src[idx];
        s += v.x * v.x + v.y * v.y + v.z * v.z + v.w * v.w;

        __nv_bfloat16 h0 = __float2bfloat16(v.x), h1 = __float2bfloat16(v.y);
        __nv_bfloat16 h2 = __float2bfloat16(v.z), h3 = __float2bfloat16(v.w);
        __nv_bfloat16 l0 = __float2bfloat16(v.x - __bfloat162float(h0));
        __nv_bfloat16 l1 = __float2bfloat16(v.y - __bfloat162float(h1));
        __nv_bfloat16 l2 = __float2bfloat16(v.z - __bfloat162float(h2));
        __nv_bfloat16 l3 = __float2bfloat16(v.w - __bfloat162float(h3));
        uint2 ph, pl;
        ph.x = (uint32_t)__bfloat16_as_ushort(h0) | ((uint32_t)__bfloat16_as_ushort(h1) << 16);
        ph.y = (uint32_t)__bfloat16_as_ushort(h2) | ((uint32_t)__bfloat16_as_ushort(h3) << 16);
        pl.x = (uint32_t)__bfloat16_as_ushort(l0) | ((uint32_t)__bfloat16_as_ushort(l1) << 16);
        pl.y = (uint32_t)__bfloat16_as_ushort(l2) | ((uint32_t)__bfloat16_as_ushort(l3) << 16);
        size_t gi = (size_t)row * 64 + idx;
        ((uint2*)g_hi)[gi] = ph;
        ((uint2*)g_lo)[gi] = pl;
    }
    #pragma unroll
    for (int o = 16; o; o >>= 1) s += __shfl_xor_sync(0xffffffffu, s, o);
    if (lane == 0) g_sq[row] = s;
}

// ---------------------------------------------------------------------------
// loss_cl + loss_ce: one warp per row
// ---------------------------------------------------------------------------
__global__ void logit_kernel(const float* __restrict__ L, const int* __restrict__ y) {
    int warp = (blockIdx.x * blockDim.x + threadIdx.x) >> 5;
    int lane = threadIdx.x & 31;
    if (warp >= N_ALL) return;
    const float* row = L + (size_t)warp * C_CLS;

    float l0 = (lane < C_CLS) ? row[lane] : -3.4e38f;
    float l1 = (lane + 32 < C_CLS) ? row[lane + 32] : -3.4e38f;
    float l2 = (lane + 64 < C_CLS) ? row[lane + 64] : -3.4e38f;

    float m = fmaxf(l0, fmaxf(l1, l2));
    #pragma unroll
    for (int o = 16; o; o >>= 1) m = fmaxf(m, __shfl_xor_sync(0xffffffffu, m, o));

    float e0 = (lane < C_CLS) ? expf(l0 - m) : 0.f;
    float e1 = (lane + 32 < C_CLS) ? expf(l1 - m) : 0.f;
    float e2 = (lane + 64 < C_CLS) ? expf(l2 - m) : 0.f;
    float s = e0 + e1 + e2;
    #pragma unroll
    for (int o = 16; o; o >>= 1) s += __shfl_xor_sync(0xffffffffu, s, o);

    if (warp < S_SRC) {
        if (lane == 0) {
            float ly = row[y[warp]];
            g_row_cl[warp] = -(ly - m - logf(s));
        }
    } else {
        float inv = 1.f / s;
        float ent = 0.f;
        if (lane < C_CLS)      { float p = e0 * inv; ent -= p * log2f(fmaxf(p, 1e-8f)); }
        if (lane + 32 < C_CLS) { float p = e1 * inv; ent -= p * log2f(fmaxf(p, 1e-8f)); }
        if (lane + 64 < C_CLS) { float p = e2 * inv; ent -= p * log2f(fmaxf(p, 1e-8f)); }
        #pragma unroll
        for (int o = 16; o; o >>= 1) ent += __shfl_xor_sync(0xffffffffu, ent, o);
        if (lane == 0) g_row_ce[warp - S_SRC] = ent;
    }
}

// ---------------------------------------------------------------------------
__device__ __forceinline__ void ins5(float (&m)[5], float v) {
    if (v < m[4]) {
        if (v < m[3]) { m[4] = m[3];
            if (v < m[2]) { m[3] = m[2];
                if (v < m[1]) { m[2] = m[1];
                    if (v < m[0]) { m[1] = m[0]; m[0] = v; } else m[1] = v;
                } else m[2] = v;
            } else m[3] = v;
        } else m[4] = v;
    }
}

// B k-slice loader: slice index it = jt*16+ks; 2x cp.async(16B) per thread
__device__ __forceinline__ void load_slice(uint32_t sb, int colbase, int it, int tid) {
    int jt = it >> 4, ks = it & 15;
    int row = tid >> 1, uu = tid & 1;
    size_t goff = (size_t)(colbase + jt * 128 + row) * 512 + (size_t)(2 * ks + uu) * 16;
    int slot = uu ^ ((row >> 2) & 1);
    uint32_t dst = sb + OFF_B + (uint32_t)((it & 3) * 8192 + row * 32 + slot * 16);
    CP_ASYNC16(dst, (const char*)g_hi + goff);
    CP_ASYNC16(dst + 4096, (const char*)g_lo + goff);
}

// ---------------------------------------------------------------------------
// Fused HMMA Gram + 5-min kernel. Grid (64 row-tiles, 2 col-halves), 256 thr.
// Tile 128x128, 8 warps in 4(m) x 2(n); warp region 32x64.
// ---------------------------------------------------------------------------
__global__ __launch_bounds__(256, 1) void dist_mma_kernel() {
    extern __shared__ char dsm_raw[];
    uint32_t raw = smem_to_u32(dsm_raw);
    uint32_t sb = (raw + 1023u) & ~1023u;
    char* dsm = dsm_raw + (sb - raw);
    float* sq_sm = (float*)(dsm + OFF_SQ);

    int tid = threadIdx.x;
    int lane = tid & 31, wid = tid >> 5;
    int wm = wid >> 1, wn = wid & 1;
    int h = blockIdx.y;
    int r0 = blockIdx.x * 128;
    int colbase = h * S_SRC;

    // column sq norms -> smem (plain loads; visible after first barrier)
    {
        const float4* src = (const float4*)(g_sq + colbase);
        float4* dst = (float4*)sq_sm;
        for (int i = tid; i < 1024; i += 256) dst[i] = src[i];
    }

    // Persistent A tile (128 rows x 256 k, hi+lo) via cp.async, swizzled:
    // byte = row*512 + ((u ^ (row&7)) * 16), u = 16B-unit index 0..31
    for (int i = tid; i < 4096; i += 256) {
        int row = i >> 5, u = i & 31;
        size_t goff = (size_t)(r0 + row) * 512 + (size_t)u * 16;
        uint32_t d = sb + OFF_A + (uint32_t)(row * 512 + ((u ^ (row & 7)) << 4));
        CP_ASYNC16(d, (const char*)g_hi + goff);
        CP_ASYNC16(d + 65536, (const char*)g_lo + goff);
    }
    load_slice(sb, colbase, 0, tid);
    CP_COMMIT();                       // group: A + slice0
    load_slice(sb, colbase, 1, tid);
    CP_COMMIT();                       // group: slice1

    // per-thread row info
    float sqa[4];
    float mn[4][5];
    #pragma unroll
    for (int q = 0; q < 4; ++q) {
        int rloc = wm * 32 + (q >> 1) * 16 + (lane >> 2) + (q & 1) * 8;
        sqa[q] = g_sq[r0 + rloc];
        #pragma unroll
        for (int p = 0; p < 5; ++p) mn[q][p] = 3.4e38f;
    }

    // precomputed ldmatrix address pieces
    uint32_t a_base[2], b_off[4];
    #pragma unroll
    for (int mi = 0; mi < 2; ++mi) {
        int arow = wm * 32 + mi * 16 + (lane & 15);
        a_base[mi] = sb + OFF_A + (uint32_t)(arow * 512);
    }
    int axor = ((wm * 32 + (lane & 15)) & 7);   // arow&7 (mi*16 doesn't change low 3 bits)
    int aklane = lane >> 4;
    #pragma unroll
    for (int g = 0; g < 4; ++g) {
        int brow = wn * 64 + g * 16 + (lane & 15);
        int bslot = (lane >> 4) ^ ((brow >> 2) & 1);
        b_off[g] = (uint32_t)(brow * 32 + bslot * 16);
    }

    float acc[2][8][4];

    const int NIT = 32 * 16;
    for (int it = 0; it < NIT; ++it) {
        if (it + 2 < NIT) load_slice(sb, colbase, it + 2, tid);
        CP_COMMIT();
        CP_WAIT2();
        __syncthreads();

        int ks = it & 15;
        if (ks == 0) {
            #pragma unroll
            for (int mi = 0; mi < 2; ++mi)
                #pragma unroll
                for (int ni = 0; ni < 8; ++ni)
                    #pragma unroll
                    for (int e = 0; e < 4; ++e) acc[mi][ni][e] = 0.f;
        }

        // A fragments (hi, lo) for both m-tiles
        uint32_t ah[2][4], al[2][4];
        uint32_t au = (uint32_t)(((2 * ks + aklane) ^ axor) << 4);
        #pragma unroll
        for (int mi = 0; mi < 2; ++mi) {
            uint32_t ad = a_base[mi] + au;
            LDSM4(ah[mi], ad);
            LDSM4(al[mi], ad + 65536);
        }
        // B fragments (hi, lo), 4 groups of 2 n-tiles
        uint32_t Bst = sb + OFF_B + (uint32_t)((it & 3) * 8192);
        uint32_t bh[4][4], bl[4][4];
        #pragma unroll
        for (int g = 0; g < 4; ++g) {
            uint32_t bd = Bst + b_off[g];
            LDSM4(bh[g], bd);
            LDSM4(bl[g], bd + 4096);
        }
        #pragma unroll
        for (int mi = 0; mi < 2; ++mi) {
            #pragma unroll
            for (int ni = 0; ni < 8; ++ni) {
                int g = ni >> 1, w = ni & 1;
                MMA16816(acc[mi][ni], ah[mi], bh[g][w], bh[g][w + 2]);
                MMA16816(acc[mi][ni], ah[mi], bl[g][w], bl[g][w + 2]);
                MMA16816(acc[mi][ni], al[mi], bh[g][w], bh[g][w + 2]);
            }
        }

        if (ks == 15) {
            int jt = it >> 4;
            const float* sqb = sq_sm + jt * 128 + wn * 64 + (lane & 3) * 2;
            #pragma unroll
            for (int ni = 0; ni < 8; ++ni) {
                float s0 = sqb[ni * 8];
                float s1 = sqb[ni * 8 + 1];
                #pragma unroll
                for (int mi = 0; mi < 2; ++mi) {
                    float d;
                    d = fmaxf(fmaf(-2.f, acc[mi][ni][0], sqa[mi * 2] + s0), 0.f);     ins5(mn[mi * 2], d);
                    d = fmaxf(fmaf(-2.f, acc[mi][ni][1], sqa[mi * 2] + s1), 0.f);     ins5(mn[mi * 2], d);
                    d = fmaxf(fmaf(-2.f, acc[mi][ni][2], sqa[mi * 2 + 1] + s0), 0.f); ins5(mn[mi * 2 + 1], d);
                    d = fmaxf(fmaf(-2.f, acc[mi][ni][3], sqa[mi * 2 + 1] + s1), 0.f); ins5(mn[mi * 2 + 1], d);
                }
            }
        }
    }

    // Merge 8 partial lists per row (4 lanes x 2 wn)
    __syncthreads();
    float* mrg = (float*)dsm;           // 128 rows x 8 slots x 5 = 20480 B (reuses sq + B)
    int slot = wn * 4 + (lane & 3);
    #pragma unroll
    for (int q = 0; q < 4; ++q) {
        int rloc = wm * 32 + (q >> 1) * 16 + (lane >> 2) + (q & 1) * 8;
        #pragma unroll
        for (int p = 0; p < 5; ++p) mrg[(rloc * 8 + slot) * 5 + p] = mn[q][p];
    }
    __syncthreads();

    if (tid < 128) {
        float s[5] = {3.4e38f, 3.4e38f, 3.4e38f, 3.4e38f, 3.4e38f};
        const float* p = mrg + tid * 40;
        for (int t = 0; t < 40; ++t) ins5(s, p[t]);
        // intra block: diag (~0 +- mma_eps) occupies s[0]; dmin = s[1]; kth incl diag = s[4]
        bool intra = ((r0 < S_SRC) == (h == 0));
        float dmin2 = intra ? s[1] : s[0];
        float kth2 = s[4];
        float sim = expf(-sqrtf(dmin2) / (2.f * (sqrtf(kth2) + 1e-8f)));
        g_simh[h * N_ALL + r0 + tid] = sim;
    }
}

// ---------------------------------------------------------------------------
// Deterministic final reduction: one block per output
// ---------------------------------------------------------------------------
__global__ void reduce_kernel(float* __restrict__ out) {
    __shared__ float sh[1024];
    int b = blockIdx.x, t = threadIdx.x;
    float a = 0.f;
    if (b == 0)      { for (int i = t; i < S_SRC; i += 1024) a += g_row_cl[i]; }
    else if (b == 1) { for (int i = t; i < S_SRC; i += 1024) a += g_row_ce[i]; }
    else             { for (int i = t; i < N_ALL; i += 1024) a += fabsf(g_simh[i] - g_simh[N_ALL + i]); }
    sh[t] = a; __syncthreads();
    for (int o = 512; o; o >>= 1) { if (t < o) sh[t] += sh[t + o]; __syncthreads(); }
    if (t == 0) out[b] = sh[0] / (float)S_SRC;
}

// ---------------------------------------------------------------------------
extern "C" void kernel_launch(void* const* d_in, const int* in_sizes, int n_in,
                              void* d_out, int out_size) {
    const float* F = (const float*)d_in[0];   // Feature_all [8192,256] f32
    const float* L = (const float*)d_in[1];   // logit_all   [8192,65]  f32
    const int*   y = (const int*)d_in[2];     // y_source    [4096]     i32
    float* out = (float*)d_out;

    cudaFuncSetAttribute(dist_mma_kernel, cudaFuncAttributeMaxDynamicSharedMemorySize, SMEM_ALLOC);

    prep_kernel<<<N_ALL / 8, 256>>>(F);       // sq norms + bf16 hi/lo split, fused
    logit_kernel<<<N_ALL / 8, 256>>>(L, y);
    dist_mma_kernel<<<dim3(64, 2), 256, SMEM_ALLOC>>>();
    reduce_kernel<<<3, 1024>>>(out);
}

// round 8
// speedup vs baseline: 10.4472x; 2.8654x over previous
#include <cuda_runtime.h>
#include <cuda_fp16.h>
#include <math.h>
#include <stdint.h>

#define N_ALL 8192
#define D_FEAT 256
#define S_SRC 4096
#define C_CLS 65

// SMEM layout (relative to 1024-aligned base)
#define OFF_SQ 0                 // 4096 f32 = 16384 B (reused as merge buffer later)
#define OFF_B  16384             // 8-slice ring x 4096 B = 32768 B
#define OFF_A  49152             // A fp16 tile 128x256 = 65536 B
#define SMEM_BYTES (49152 + 65536)
#define SMEM_ALLOC (SMEM_BYTES + 1024)

// ---------------------------------------------------------------------------
// Scratch (__device__ globals: allocation-free rule)
// ---------------------------------------------------------------------------
__device__ float g_sq[N_ALL];
__device__ float g_row_cl[S_SRC];
__device__ float g_row_ce[S_SRC];
__device__ float g_simh[2 * N_ALL];
__device__ __align__(16) __half g_h16[N_ALL * D_FEAT];

// ---------------------------------------------------------------------------
// PTX helpers (baseline PTX only — nothing arch-'a'-gated)
// ---------------------------------------------------------------------------
__device__ __forceinline__ uint32_t smem_to_u32(const void* p) {
    uint32_t a;
    asm("{ .reg .u64 t; cvta.to.shared.u64 t, %1; cvt.u32.u64 %0, t; }" : "=r"(a) : "l"(p));
    return a;
}

#define CP_ASYNC16(DST, SRC) \
    asm volatile("cp.async.cg.shared.global [%0], [%1], 16;" :: "r"(DST), "l"(SRC) : "memory")
#define CP_COMMIT() asm volatile("cp.async.commit_group;" ::: "memory")
#define CP_WAIT2()  asm volatile("cp.async.wait_group 2;" ::: "memory")

#define LDSM4(R, ADDR) \
    asm volatile("ldmatrix.sync.aligned.m8n8.x4.shared.b16 {%0,%1,%2,%3}, [%4];" \
        : "=r"((R)[0]), "=r"((R)[1]), "=r"((R)[2]), "=r"((R)[3]) : "r"(ADDR))

#define MMA16816(D, A, B0, B1) \
    asm volatile("mma.sync.aligned.m16n8k16.row.col.f32.f16.f16.f32 " \
        "{%0,%1,%2,%3}, {%4,%5,%6,%7}, {%8,%9}, {%0,%1,%2,%3};" \
        : "+f"((D)[0]), "+f"((D)[1]), "+f"((D)[2]), "+f"((D)[3]) \
        : "r"((A)[0]), "r"((A)[1]), "r"((A)[2]), "r"((A)[3]), "r"(B0), "r"(B1))

// ---------------------------------------------------------------------------
// Fused: row squared norms (fp32, exact) + f32 -> fp16 image (one warp per row)
// ---------------------------------------------------------------------------
__global__ void prep_kernel(const float* __restrict__ F) {
    int row = (blockIdx.x * blockDim.x + threadIdx.x) >> 5;
    int lane = threadIdx.x & 31;
    if (row >= N_ALL) return;
    const float4* src = (const float4*)(F + (size_t)row * D_FEAT);
    float s = 0.f;
    #pragma unroll
    for (int i = 0; i < 2; ++i) {
        int idx = lane + 32 * i;                 // float4 index within row (0..63)
        float4 v = src[idx];
        s += v.x * v.x + v.y * v.y + v.z * v.z + v.w * v.w;

        __half h0 = __float2half(v.x), h1 = __float2half(v.y);
        __half h2 = __float2half(v.z), h3 = __float2half(v.w);
        uint2 ph;
        ph.x = (uint32_t)__half_as_ushort(h0) | ((uint32_t)__half_as_ushort(h1) << 16);
        ph.y = (uint32_t)__half_as_ushort(h2) | ((uint32_t)__half_as_ushort(h3) << 16);
        ((uint2*)g_h16)[(size_t)row * 64 + idx] = ph;
    }
    #pragma unroll
    for (int o = 16; o; o >>= 1) s += __shfl_xor_sync(0xffffffffu, s, o);
    if (lane == 0) g_sq[row] = s;
}

// ---------------------------------------------------------------------------
// loss_cl + loss_ce: one warp per row
// ---------------------------------------------------------------------------
__global__ void logit_kernel(const float* __restrict__ L, const int* __restrict__ y) {
    int warp = (blockIdx.x * blockDim.x + threadIdx.x) >> 5;
    int lane = threadIdx.x & 31;
    if (warp >= N_ALL) return;
    const float* row = L + (size_t)warp * C_CLS;

    float l0 = (lane < C_CLS) ? row[lane] : -3.4e38f;
    float l1 = (lane + 32 < C_CLS) ? row[lane + 32] : -3.4e38f;
    float l2 = (lane + 64 < C_CLS) ? row[lane + 64] : -3.4e38f;

    float m = fmaxf(l0, fmaxf(l1, l2));
    #pragma unroll
    for (int o = 16; o; o >>= 1) m = fmaxf(m, __shfl_xor_sync(0xffffffffu, m, o));

    float e0 = (lane < C_CLS) ? expf(l0 - m) : 0.f;
    float e1 = (lane + 32 < C_CLS) ? expf(l1 - m) : 0.f;
    float e2 = (lane + 64 < C_CLS) ? expf(l2 - m) : 0.f;
    float s = e0 + e1 + e2;
    #pragma unroll
    for (int o = 16; o; o >>= 1) s += __shfl_xor_sync(0xffffffffu, s, o);

    if (warp < S_SRC) {
        if (lane == 0) {
            float ly = row[y[warp]];
            g_row_cl[warp] = -(ly - m - logf(s));
        }
    } else {
        float inv = 1.f / s;
        float ent = 0.f;
        if (lane < C_CLS)      { float p = e0 * inv; ent -= p * log2f(fmaxf(p, 1e-8f)); }
        if (lane + 32 < C_CLS) { float p = e1 * inv; ent -= p * log2f(fmaxf(p, 1e-8f)); }
        if (lane + 64 < C_CLS) { float p = e2 * inv; ent -= p * log2f(fmaxf(p, 1e-8f)); }
        #pragma unroll
        for (int o = 16; o; o >>= 1) ent += __shfl_xor_sync(0xffffffffu, ent, o);
        if (lane == 0) g_row_ce[warp - S_SRC] = ent;
    }
}

// ---------------------------------------------------------------------------
__device__ __forceinline__ void ins5(float (&m)[5], float v) {
    if (v < m[4]) {
        if (v < m[3]) { m[4] = m[3];
            if (v < m[2]) { m[3] = m[2];
                if (v < m[1]) { m[2] = m[1];
                    if (v < m[0]) { m[1] = m[0]; m[0] = v; } else m[1] = v;
                } else m[2] = v;
            } else m[3] = v;
        } else m[4] = v;
    }
}

// Load the two 16k-slices (2*it, 2*it+1) for iteration 'it' into the 8-slot ring.
// One cp.async(16B) per thread per slice.
__device__ __forceinline__ void load_pair(uint32_t sb, int colbase, int it, int tid) {
    int row = tid >> 1, uu = tid & 1;
    int slot = uu ^ ((row >> 2) & 1);
    #pragma unroll
    for (int c = 0; c < 2; ++c) {
        int s = 2 * it + c;
        int jt = s >> 4, ks = s & 15;
        size_t goff = (size_t)(colbase + jt * 128 + row) * 512 + (size_t)ks * 32 + (size_t)uu * 16;
        uint32_t dst = sb + OFF_B + (uint32_t)((s & 7) * 4096 + row * 32 + slot * 16);
        CP_ASYNC16(dst, (const char*)g_h16 + goff);
    }
}

// ---------------------------------------------------------------------------
// Fused HMMA Gram + 5-min kernel. Grid (64 row-tiles, 2 col-halves), 256 thr.
// Tile 128x128, 8 warps in 4(m) x 2(n); warp region 32x64. Pure fp16 Gram,
// k-step 32 per barrier (2 x 16k chunks), fp32 norms outside the MMA.
// ---------------------------------------------------------------------------
__global__ __launch_bounds__(256, 1) void dist_mma_kernel() {
    extern __shared__ char dsm_raw[];
    uint32_t raw = smem_to_u32(dsm_raw);
    uint32_t sb = (raw + 1023u) & ~1023u;
    char* dsm = dsm_raw + (sb - raw);
    float* sq_sm = (float*)(dsm + OFF_SQ);

    int tid = threadIdx.x;
    int lane = tid & 31, wid = tid >> 5;
    int wm = wid >> 1, wn = wid & 1;
    int h = blockIdx.y;
    int r0 = blockIdx.x * 128;
    int colbase = h * S_SRC;

    // column sq norms -> smem (plain loads; visible after first barrier)
    {
        const float4* src = (const float4*)(g_sq + colbase);
        float4* dst = (float4*)sq_sm;
        for (int i = tid; i < 1024; i += 256) dst[i] = src[i];
    }

    // Persistent A tile (128 rows x 256 k fp16) via cp.async, swizzled:
    // byte = row*512 + ((u ^ (row&7)) * 16), u = 16B-unit index 0..31
    for (int i = tid; i < 4096; i += 256) {
        int row = i >> 5, u = i & 31;
        size_t goff = (size_t)(r0 + row) * 512 + (size_t)u * 16;
        uint32_t d = sb + OFF_A + (uint32_t)(row * 512 + ((u ^ (row & 7)) << 4));
        CP_ASYNC16(d, (const char*)g_h16 + goff);
    }
    load_pair(sb, colbase, 0, tid);
    CP_COMMIT();                       // group: A + pair0
    load_pair(sb, colbase, 1, tid);
    CP_COMMIT();                       // group: pair1

    // per-thread row info
    float sqa[4];
    float mn[4][5];
    #pragma unroll
    for (int q = 0; q < 4; ++q) {
        int rloc = wm * 32 + (q >> 1) * 16 + (lane >> 2) + (q & 1) * 8;
        sqa[q] = g_sq[r0 + rloc];
        #pragma unroll
        for (int p = 0; p < 5; ++p) mn[q][p] = 3.4e38f;
    }

    // precomputed ldmatrix address pieces
    uint32_t a_base[2], b_off[4];
    #pragma unroll
    for (int mi = 0; mi < 2; ++mi) {
        int arow = wm * 32 + mi * 16 + (lane & 15);
        a_base[mi] = sb + OFF_A + (uint32_t)(arow * 512);
    }
    int axor = ((wm * 32 + (lane & 15)) & 7);   // arow&7 (mi*16 doesn't change low 3 bits)
    int aklane = lane >> 4;
    #pragma unroll
    for (int g = 0; g < 4; ++g) {
        int brow = wn * 64 + g * 16 + (lane & 15);
        int bslot = (lane >> 4) ^ ((brow >> 2) & 1);
        b_off[g] = (uint32_t)(brow * 32 + bslot * 16);
    }

    float acc[2][8][4];

    const int NIT = 256;               // 32 col-tiles x 8 k-iters (32k per iter)
    for (int it = 0; it < NIT; ++it) {
        if (it + 2 < NIT) load_pair(sb, colbase, it + 2, tid);
        CP_COMMIT();
        CP_WAIT2();
        __syncthreads();

        int kk = it & 7;
        if (kk == 0) {
            #pragma unroll
            for (int mi = 0; mi < 2; ++mi)
                #pragma unroll
                for (int ni = 0; ni < 8; ++ni)
                    #pragma unroll
                    for (int e = 0; e < 4; ++e) acc[mi][ni][e] = 0.f;
        }

        #pragma unroll
        for (int c = 0; c < 2; ++c) {
            int ks = 2 * kk + c;       // 16k chunk within feature dim
            uint32_t au = (uint32_t)(((2 * ks + aklane) ^ axor) << 4);
            uint32_t ah0[4], ah1[4];
            LDSM4(ah0, a_base[0] + au);
            LDSM4(ah1, a_base[1] + au);
            uint32_t Bst = sb + OFF_B + (uint32_t)(((2 * it + c) & 7) * 4096);
            uint32_t bh[4][4];
            #pragma unroll
            for (int g = 0; g < 4; ++g) LDSM4(bh[g], Bst + b_off[g]);
            #pragma unroll
            for (int ni = 0; ni < 8; ++ni) {
                int g = ni >> 1, w = ni & 1;
                MMA16816(acc[0][ni], ah0, bh[g][w], bh[g][w + 2]);
                MMA16816(acc[1][ni], ah1, bh[g][w], bh[g][w + 2]);
            }
        }

        if (kk == 7) {
            int jt = it >> 3;
            const float* sqb = sq_sm + jt * 128 + wn * 64 + (lane & 3) * 2;
            #pragma unroll
            for (int ni = 0; ni < 8; ++ni) {
                float s0 = sqb[ni * 8];
                float s1 = sqb[ni * 8 + 1];
                #pragma unroll
                for (int mi = 0; mi < 2; ++mi) {
                    float d;
                    d = fmaxf(fmaf(-2.f, acc[mi][ni][0], sqa[mi * 2] + s0), 0.f);     ins5(mn[mi * 2], d);
                    d = fmaxf(fmaf(-2.f, acc[mi][ni][1], sqa[mi * 2] + s1), 0.f);     ins5(mn[mi * 2], d);
                    d = fmaxf(fmaf(-2.f, acc[mi][ni][2], sqa[mi * 2 + 1] + s0), 0.f); ins5(mn[mi * 2 + 1], d);
                    d = fmaxf(fmaf(-2.f, acc[mi][ni][3], sqa[mi * 2 + 1] + s1), 0.f); ins5(mn[mi * 2 + 1], d);
                }
            }
        }
    }

    // Merge 8 partial lists per row (4 lanes x 2 wn)
    __syncthreads();
    float* mrg = (float*)dsm;           // 128 rows x 8 slots x 5 = 20480 B (reuses sq+B)
    int slot = wn * 4 + (lane & 3);
    #pragma unroll
    for (int q = 0; q < 4; ++q) {
        int rloc = wm * 32 + (q >> 1) * 16 + (lane >> 2) + (q & 1) * 8;
        #pragma unroll
        for (int p = 0; p < 5; ++p) mrg[(rloc * 8 + slot) * 5 + p] = mn[q][p];
    }
    __syncthreads();

    if (tid < 128) {
        float s[5] = {3.4e38f, 3.4e38f, 3.4e38f, 3.4e38f, 3.4e38f};
        const float* p = mrg + tid * 40;
        for (int t = 0; t < 40; ++t) ins5(s, p[t]);
        // intra block: diag (~0 +- fp16 eps, clamped) occupies s[0];
        // dmin = s[1]; kth incl diag = s[4]
        bool intra = ((r0 < S_SRC) == (h == 0));
        float dmin2 = intra ? s[1] : s[0];
        float kth2 = s[4];
        float sim = expf(-sqrtf(dmin2) / (2.f * (sqrtf(kth2) + 1e-8f)));
        g_simh[h * N_ALL + r0 + tid] = sim;
    }
}

// ---------------------------------------------------------------------------
// Deterministic final reduction: one block per output
// ---------------------------------------------------------------------------
__global__ void reduce_kernel(float* __restrict__ out) {
    __shared__ float sh[1024];
    int b = blockIdx.x, t = threadIdx.x;
    float a = 0.f;
    if (b == 0)      { for (int i = t; i < S_SRC; i += 1024) a += g_row_cl[i]; }
    else if (b == 1) { for (int i = t; i < S_SRC; i += 1024) a += g_row_ce[i]; }
    else             { for (int i = t; i < N_ALL; i += 1024) a += fabsf(g_simh[i] - g_simh[N_ALL + i]); }
    sh[t] = a; __syncthreads();
    for (int o = 512; o; o >>= 1) { if (t < o) sh[t] += sh[t + o]; __syncthreads(); }
    if (t == 0) out[b] = sh[0] / (float)S_SRC;
}

// ---------------------------------------------------------------------------
extern "C" void kernel_launch(void* const* d_in, const int* in_sizes, int n_in,
                              void* d_out, int out_size) {
    const float* F = (const float*)d_in[0];   // Feature_all [8192,256] f32
    const float* L = (const float*)d_in[1];   // logit_all   [8192,65]  f32
    const int*   y = (const int*)d_in[2];     // y_source    [4096]     i32
    float* out = (float*)d_out;

    cudaFuncSetAttribute(dist_mma_kernel, cudaFuncAttributeMaxDynamicSharedMemorySize, SMEM_ALLOC);

    prep_kernel<<<N_ALL / 8, 256>>>(F);       // sq norms (fp32) + fp16 image, fused
    logit_kernel<<<N_ALL / 8, 256>>>(L, y);
    dist_mma_kernel<<<dim3(64, 2), 256, SMEM_ALLOC>>>();
    reduce_kernel<<<3, 1024>>>(out);
}

// round 11
// speedup vs baseline: 10.6584x; 1.0202x over previous
#include <cuda_runtime.h>
#include <cuda_fp16.h>
#include <math.h>
#include <stdint.h>

#define N_ALL 8192
#define D_FEAT 256
#define S_SRC 4096
#define C_CLS 65
#define NT 64                    // 128-row tiles per dim
#define NTILES 2080              // NT*(NT+1)/2

// SMEM layout (relative to 1024-aligned base)
#define OFF_A   0                // A fp16 128x256 swizzled, 65536 B
#define OFF_Bt  65536            // B fp16 128x256 swizzled, 65536 B
#define OFF_D   131072           // dot buffer fp32 128x129 = 66048 B
#define OFF_SQI 197120           // 128 f32
#define OFF_SQJ 197632           // 128 f32
#define SMEM_BYTES 198144
#define SMEM_ALLOC (SMEM_BYTES + 1024)

// ---------------------------------------------------------------------------
// Scratch (__device__ globals: allocation-free rule)
// ---------------------------------------------------------------------------
__device__ float g_sq[N_ALL];
__device__ float g_row_cl[S_SRC];
__device__ float g_row_ce[S_SRC];
__device__ float g_simh[2 * N_ALL];
__device__ float g_part[2 * N_ALL * 32 * 5];     // per (half,row,coltile) 5-min partials
__device__ __align__(16) __half g_h16[N_ALL * D_FEAT];

// ---------------------------------------------------------------------------
// PTX helpers (baseline PTX only)
// ---------------------------------------------------------------------------
__device__ __forceinline__ uint32_t smem_to_u32(const void* p) {
    uint32_t a;
    asm("{ .reg .u64 t; cvta.to.shared.u64 t, %1; cvt.u32.u64 %0, t; }" : "=r"(a) : "l"(p));
    return a;
}

#define CP_ASYNC16(DST, SRC) \
    asm volatile("cp.async.cg.shared.global [%0], [%1], 16;" :: "r"(DST), "l"(SRC) : "memory")
#define CP_COMMIT() asm volatile("cp.async.commit_group;" ::: "memory")
#define CP_WAIT0()  asm volatile("cp.async.wait_group 0;" ::: "memory")

#define LDSM4(R, ADDR) \
    asm volatile("ldmatrix.sync.aligned.m8n8.x4.shared.b16 {%0,%1,%2,%3}, [%4];" \
        : "=r"((R)[0]), "=r"((R)[1]), "=r"((R)[2]), "=r"((R)[3]) : "r"(ADDR))

#define MMA16816(D, A, B0, B1) \
    asm volatile("mma.sync.aligned.m16n8k16.row.col.f32.f16.f16.f32 " \
        "{%0,%1,%2,%3}, {%4,%5,%6,%7}, {%8,%9}, {%0,%1,%2,%3};" \
        : "+f"((D)[0]), "+f"((D)[1]), "+f"((D)[2]), "+f"((D)[3]) \
        : "r"((A)[0]), "r"((A)[1]), "r"((A)[2]), "r"((A)[3]), "r"(B0), "r"(B1))

// ---------------------------------------------------------------------------
// Fused: row squared norms (fp32, exact) + f32 -> fp16 image (one warp per row)
// ---------------------------------------------------------------------------
__global__ void prep_kernel(const float* __restrict__ F) {
    int row = (blockIdx.x * blockDim.x + threadIdx.x) >> 5;
    int lane = threadIdx.x & 31;
    if (row >= N_ALL) return;
    const float4* src = (const float4*)(F + (size_t)row * D_FEAT);
    float s = 0.f;
    #pragma unroll
    for (int i = 0; i < 2; ++i) {
        int idx = lane + 32 * i;
        float4 v = src[idx];
        s += v.x * v.x + v.y * v.y + v.z * v.z + v.w * v.w;
        __half h0 = __float2half(v.x), h1 = __float2half(v.y);
        __half h2 = __float2half(v.z), h3 = __float2half(v.w);
        uint2 ph;
        ph.x = (uint32_t)__half_as_ushort(h0) | ((uint32_t)__half_as_ushort(h1) << 16);
        ph.y = (uint32_t)__half_as_ushort(h2) | ((uint32_t)__half_as_ushort(h3) << 16);
        ((uint2*)g_h16)[(size_t)row * 64 + idx] = ph;
    }
    #pragma unroll
    for (int o = 16; o; o >>= 1) s += __shfl_xor_sync(0xffffffffu, s, o);
    if (lane == 0) g_sq[row] = s;
}

// ---------------------------------------------------------------------------
// loss_cl + loss_ce: one warp per row
// ---------------------------------------------------------------------------
__global__ void logit_kernel(const float* __restrict__ L, const int* __restrict__ y) {
    int warp = (blockIdx.x * blockDim.x + threadIdx.x) >> 5;
    int lane = threadIdx.x & 31;
    if (warp >= N_ALL) return;
    const float* row = L + (size_t)warp * C_CLS;

    float l0 = (lane < C_CLS) ? row[lane] : -3.4e38f;
    float l1 = (lane + 32 < C_CLS) ? row[lane + 32] : -3.4e38f;
    float l2 = (lane + 64 < C_CLS) ? row[lane + 64] : -3.4e38f;

    float m = fmaxf(l0, fmaxf(l1, l2));
    #pragma unroll
    for (int o = 16; o; o >>= 1) m = fmaxf(m, __shfl_xor_sync(0xffffffffu, m, o));

    float e0 = (lane < C_CLS) ? expf(l0 - m) : 0.f;
    float e1 = (lane + 32 < C_CLS) ? expf(l1 - m) : 0.f;
    float e2 = (lane + 64 < C_CLS) ? expf(l2 - m) : 0.f;
    float s = e0 + e1 + e2;
    #pragma unroll
    for (int o = 16; o; o >>= 1) s += __shfl_xor_sync(0xffffffffu, s, o);

    if (warp < S_SRC) {
        if (lane == 0) {
            float ly = row[y[warp]];
            g_row_cl[warp] = -(ly - m - logf(s));
        }
    } else {
        float inv = 1.f / s;
        float ent = 0.f;
        if (lane < C_CLS)      { float p = e0 * inv; ent -= p * log2f(fmaxf(p, 1e-8f)); }
        if (lane + 32 < C_CLS) { float p = e1 * inv; ent -= p * log2f(fmaxf(p, 1e-8f)); }
        if (lane + 64 < C_CLS) { float p = e2 * inv; ent -= p * log2f(fmaxf(p, 1e-8f)); }
        #pragma unroll
        for (int o = 16; o; o >>= 1) ent += __shfl_xor_sync(0xffffffffu, ent, o);
        if (lane == 0) g_row_ce[warp - S_SRC] = ent;
    }
}

// ---------------------------------------------------------------------------
__device__ __forceinline__ void ins5(float (&m)[5], float v) {
    if (v < m[4]) {
        if (v < m[3]) { m[4] = m[3];
            if (v < m[2]) { m[3] = m[2];
                if (v < m[1]) { m[2] = m[1];
                    if (v < m[0]) { m[1] = m[0]; m[0] = v; } else m[1] = v;
                } else m[2] = v;
            } else m[3] = v;
        } else m[4] = v;
    }
}

// ---------------------------------------------------------------------------
// Symmetric-tile HMMA Gram + dual-scan 5-min kernel.
// Grid: 2080 CTAs, one upper-triangle 128x128 tile each. 256 threads,
// 8 warps in 4(m) x 2(n). Barrier-free 16-chunk k-loop; dot tile staged to
// SMEM; row scan (thread t<128) + col scan (thread t>=128, J!=I) in parallel.
// ---------------------------------------------------------------------------
__global__ __launch_bounds__(256, 1) void dist_mma_kernel() {
    extern __shared__ char dsm_raw[];
    uint32_t raw = smem_to_u32(dsm_raw);
    uint32_t sb = (raw + 1023u) & ~1023u;
    char* dsm = dsm_raw + (sb - raw);
    float* Dsm = (float*)(dsm + OFF_D);
    float* sqI = (float*)(dsm + OFF_SQI);
    float* sqJ = (float*)(dsm + OFF_SQJ);

    int tid = threadIdx.x;
    int lane = tid & 31, wid = tid >> 5;
    int wm = wid >> 1, wn = wid & 1;

    // decode upper-triangle tile (I, J>=I) from linear blockIdx.x
    int I = 0, rem = blockIdx.x;
    while (rem >= NT - I) { rem -= NT - I; ++I; }
    int J = I + rem;
    int rI = I * 128, rJ = J * 128;

    // stage sq norms
    if (tid < 128) sqI[tid] = g_sq[rI + tid];
    else           sqJ[tid - 128] = g_sq[rJ + tid - 128];

    // A tile (rows of I) + B tile (rows of J), fp16, XOR-swizzled:
    // byte = row*512 + ((u ^ (row&7)) * 16), u = 16B-unit 0..31
    for (int i = tid; i < 4096; i += 256) {
        int row = i >> 5, u = i & 31;
        uint32_t sw = (uint32_t)(row * 512 + ((u ^ (row & 7)) << 4));
        CP_ASYNC16(sb + OFF_A + sw,  (const char*)g_h16 + (size_t)(rI + row) * 512 + (size_t)u * 16);
        CP_ASYNC16(sb + OFF_Bt + sw, (const char*)g_h16 + (size_t)(rJ + row) * 512 + (size_t)u * 16);
    }
    CP_COMMIT();
    CP_WAIT0();
    __syncthreads();

    // ldmatrix bases
    uint32_t a_base[2], b_base[4];
    #pragma unroll
    for (int mi = 0; mi < 2; ++mi)
        a_base[mi] = sb + OFF_A + (uint32_t)((wm * 32 + mi * 16 + (lane & 15)) * 512);
    #pragma unroll
    for (int g = 0; g < 4; ++g)
        b_base[g] = sb + OFF_Bt + (uint32_t)((wn * 64 + g * 16 + (lane & 15)) * 512);
    int sxor = (lane & 15) & 7;         // row&7 for both A and B bases
    int klane = lane >> 4;

    float acc[2][8][4];
    #pragma unroll
    for (int mi = 0; mi < 2; ++mi)
        #pragma unroll
        for (int ni = 0; ni < 8; ++ni)
            #pragma unroll
            for (int e = 0; e < 4; ++e) acc[mi][ni][e] = 0.f;

    // barrier-free k-loop: 16 chunks of k16
    #pragma unroll 4
    for (int ks = 0; ks < 16; ++ks) {
        uint32_t au = (uint32_t)(((2 * ks + klane) ^ sxor) << 4);
        uint32_t ah[2][4], bh[4][4];
        LDSM4(ah[0], a_base[0] + au);
        LDSM4(ah[1], a_base[1] + au);
        #pragma unroll
        for (int g = 0; g < 4; ++g) LDSM4(bh[g], b_base[g] + au);
        #pragma unroll
        for (int ni = 0; ni < 8; ++ni) {
            int g = ni >> 1, w = ni & 1;
            MMA16816(acc[0][ni], ah[0], bh[g][w], bh[g][w + 2]);
            MMA16816(acc[1][ni], ah[1], bh[g][w], bh[g][w + 2]);
        }
    }

    // stage raw dots to SMEM [row][col], pad 129 (conflict-free dual scans)
    #pragma unroll
    for (int mi = 0; mi < 2; ++mi)
        #pragma unroll
        for (int ni = 0; ni < 8; ++ni)
            #pragma unroll
            for (int e = 0; e < 4; ++e) {
                int row = wm * 32 + mi * 16 + (lane >> 2) + (e >> 1) * 8;
                int col = wn * 64 + ni * 8 + (lane & 3) * 2 + (e & 1);
                Dsm[row * 129 + col] = acc[mi][ni][e];
            }
    __syncthreads();

    if (tid < 128) {
        // row scan: row (rI+tid) vs cols of J
        float sqi = sqI[tid];
        float s[5] = {3.4e38f, 3.4e38f, 3.4e38f, 3.4e38f, 3.4e38f};
        const float* drow = Dsm + tid * 129;
        for (int c = 0; c < 128; ++c)
            ins5(s, fmaxf(fmaf(-2.f, drow[c], sqi + sqJ[c]), 0.f));
        float* dst = g_part + (((size_t)(J >> 5) * N_ALL + rI + tid) * 32 + (J & 31)) * 5;
        #pragma unroll
        for (int p = 0; p < 5; ++p) dst[p] = s[p];
    } else if (I != J) {
        // col scan: row (rJ+c) vs cols of I (transposed view)
        int c = tid - 128;
        float sqj = sqJ[c];
        float s[5] = {3.4e38f, 3.4e38f, 3.4e38f, 3.4e38f, 3.4e38f};
        const float* dcol = Dsm + c;
        for (int r = 0; r < 128; ++r)
            ins5(s, fmaxf(fmaf(-2.f, dcol[r * 129], sqj + sqI[r]), 0.f));
        float* dst = g_part + (((size_t)(I >> 5) * N_ALL + rJ + c) * 32 + (I & 31)) * 5;
        #pragma unroll
        for (int p = 0; p < 5; ++p) dst[p] = s[p];
    }
}

// ---------------------------------------------------------------------------
// Merge 32 per-coltile partials per (half,row) -> sim value
// ---------------------------------------------------------------------------
__global__ void merge_kernel() {
    int gid = blockIdx.x * 256 + threadIdx.x;    // 16384 = 2 * 8192
    int h = gid >> 13, r = gid & (N_ALL - 1);
    const float* p = g_part + (size_t)gid * 160;
    float s[5] = {3.4e38f, 3.4e38f, 3.4e38f, 3.4e38f, 3.4e38f};
    for (int i = 0; i < 160; ++i) ins5(s, p[i]);
    // intra half: diag (~0, fp16 eps, clamped) occupies s[0];
    // dmin = s[1]; 5th smallest incl diag = s[4] (matches reference top_k)
    bool intra = ((r < S_SRC) == (h == 0));
    float dmin2 = intra ? s[1] : s[0];
    float kth2 = s[4];
    g_simh[h * N_ALL + r] = expf(-sqrtf(dmin2) / (2.f * (sqrtf(kth2) + 1e-8f)));
}

// ---------------------------------------------------------------------------
// Deterministic final reduction: one block per output
// ---------------------------------------------------------------------------
__global__ void reduce_kernel(float* __restrict__ out) {
    __shared__ float sh[1024];
    int b = blockIdx.x, t = threadIdx.x;
    float a = 0.f;
    if (b == 0)      { for (int i = t; i < S_SRC; i += 1024) a += g_row_cl[i]; }
    else if (b == 1) { for (int i = t; i < S_SRC; i += 1024) a += g_row_ce[i]; }
    else             { for (int i = t; i < N_ALL; i += 1024) a += fabsf(g_simh[i] - g_simh[N_ALL + i]); }
    sh[t] = a; __syncthreads();
    for (int o = 512; o; o >>= 1) { if (t < o) sh[t] += sh[t + o]; __syncthreads(); }
    if (t == 0) out[b] = sh[0] / (float)S_SRC;
}

// ---------------------------------------------------------------------------
extern "C" void kernel_launch(void* const* d_in, const int* in_sizes, int n_in,
                              void* d_out, int out_size) {
    const float* F = (const float*)d_in[0];   // Feature_all [8192,256] f32
    const float* L = (const float*)d_in[1];   // logit_all   [8192,65]  f32
    const int*   y = (const int*)d_in[2];     // y_source    [4096]     i32
    float* out = (float*)d_out;

    cudaFuncSetAttribute(dist_mma_kernel, cudaFuncAttributeMaxDynamicSharedMemorySize, SMEM_ALLOC);

    prep_kernel<<<N_ALL / 8, 256>>>(F);       // sq norms (fp32) + fp16 image, fused
    logit_kernel<<<N_ALL / 8, 256>>>(L, y);
    dist_mma_kernel<<<NTILES, 256, SMEM_ALLOC>>>();
    merge_kernel<<<64, 256>>>();
    reduce_kernel<<<3, 1024>>>(out);
}

// round 12
// speedup vs baseline: 10.9115x; 1.0237x over previous
#include <cuda_runtime.h>
#include <cuda_fp16.h>
#include <math.h>
#include <stdint.h>

#define N_ALL 8192
#define D_FEAT 256
#define S_SRC 4096
#define C_CLS 65
#define NT 64                    // 128-row tiles per dim
#define NTILES 2080              // NT*(NT+1)/2
#define NCTA 148

// SMEM layout (relative to 1024-aligned base)
#define OFF_A   0                // A fp16 128x256 swizzled, 65536 B
#define OFF_Bt  65536            // B fp16 128x256 swizzled, 65536 B
#define OFF_D   131072           // dot buffer fp32 128x129 = 66048 B
#define OFF_SQI 197120           // 128 f32
#define OFF_SQJ 197632           // 128 f32
#define SMEM_BYTES 198144
#define SMEM_ALLOC (SMEM_BYTES + 1024)

// ---------------------------------------------------------------------------
// Scratch (__device__ globals: allocation-free rule)
// ---------------------------------------------------------------------------
__device__ float g_sq[N_ALL];
__device__ float g_row_cl[S_SRC];
__device__ float g_row_ce[S_SRC];
__device__ float g_simh[2 * N_ALL];
__device__ float g_part[2 * N_ALL * 32 * 5];     // per (half,row,coltile) 5-min partials
__device__ __align__(16) __half g_h16[N_ALL * D_FEAT];

// ---------------------------------------------------------------------------
// PTX helpers (baseline PTX only)
// ---------------------------------------------------------------------------
__device__ __forceinline__ uint32_t smem_to_u32(const void* p) {
    uint32_t a;
    asm("{ .reg .u64 t; cvta.to.shared.u64 t, %1; cvt.u32.u64 %0, t; }" : "=r"(a) : "l"(p));
    return a;
}

#define CP_ASYNC16(DST, SRC) \
    asm volatile("cp.async.cg.shared.global [%0], [%1], 16;" :: "r"(DST), "l"(SRC) : "memory")
#define CP_COMMIT() asm volatile("cp.async.commit_group;" ::: "memory")
#define CP_WAIT0()  asm volatile("cp.async.wait_group 0;" ::: "memory")

#define LDSM4(R, ADDR) \
    asm volatile("ldmatrix.sync.aligned.m8n8.x4.shared.b16 {%0,%1,%2,%3}, [%4];" \
        : "=r"((R)[0]), "=r"((R)[1]), "=r"((R)[2]), "=r"((R)[3]) : "r"(ADDR))

#define MMA16816(D, A, B0, B1) \
    asm volatile("mma.sync.aligned.m16n8k16.row.col.f32.f16.f16.f32 " \
        "{%0,%1,%2,%3}, {%4,%5,%6,%7}, {%8,%9}, {%0,%1,%2,%3};" \
        : "+f"((D)[0]), "+f"((D)[1]), "+f"((D)[2]), "+f"((D)[3]) \
        : "r"((A)[0]), "r"((A)[1]), "r"((A)[2]), "r"((A)[3]), "r"(B0), "r"(B1))

// ---------------------------------------------------------------------------
// Fused: row squared norms (fp32, exact) + f32 -> fp16 image (one warp per row)
// ---------------------------------------------------------------------------
__global__ void prep_kernel(const float* __restrict__ F) {
    int row = (blockIdx.x * blockDim.x + threadIdx.x) >> 5;
    int lane = threadIdx.x & 31;
    if (row >= N_ALL) return;
    const float4* src = (const float4*)(F + (size_t)row * D_FEAT);
    float s = 0.f;
    #pragma unroll
    for (int i = 0; i < 2; ++i) {
        int idx = lane + 32 * i;
        float4 v = src[idx];
        s += v.x * v.x + v.y * v.y + v.z * v.z + v.w * v.w;
        __half h0 = __float2half(v.x), h1 = __float2half(v.y);
        __half h2 = __float2half(v.z), h3 = __float2half(v.w);
        uint2 ph;
        ph.x = (uint32_t)__half_as_ushort(h0) | ((uint32_t)__half_as_ushort(h1) << 16);
        ph.y = (uint32_t)__half_as_ushort(h2) | ((uint32_t)__half_as_ushort(h3) << 16);
        ((uint2*)g_h16)[(size_t)row * 64 + idx] = ph;
    }
    #pragma unroll
    for (int o = 16; o; o >>= 1) s += __shfl_xor_sync(0xffffffffu, s, o);
    if (lane == 0) g_sq[row] = s;
}

// ---------------------------------------------------------------------------
// loss_cl + loss_ce: one warp per row
// ---------------------------------------------------------------------------
__global__ void logit_kernel(const float* __restrict__ L, const int* __restrict__ y) {
    int warp = (blockIdx.x * blockDim.x + threadIdx.x) >> 5;
    int lane = threadIdx.x & 31;
    if (warp >= N_ALL) return;
    const float* row = L + (size_t)warp * C_CLS;

    float l0 = (lane < C_CLS) ? row[lane] : -3.4e38f;
    float l1 = (lane + 32 < C_CLS) ? row[lane + 32] : -3.4e38f;
    float l2 = (lane + 64 < C_CLS) ? row[lane + 64] : -3.4e38f;

    float m = fmaxf(l0, fmaxf(l1, l2));
    #pragma unroll
    for (int o = 16; o; o >>= 1) m = fmaxf(m, __shfl_xor_sync(0xffffffffu, m, o));

    float e0 = (lane < C_CLS) ? expf(l0 - m) : 0.f;
    float e1 = (lane + 32 < C_CLS) ? expf(l1 - m) : 0.f;
    float e2 = (lane + 64 < C_CLS) ? expf(l2 - m) : 0.f;
    float s = e0 + e1 + e2;
    #pragma unroll
    for (int o = 16; o; o >>= 1) s += __shfl_xor_sync(0xffffffffu, s, o);

    if (warp < S_SRC) {
        if (lane == 0) {
            float ly = row[y[warp]];
            g_row_cl[warp] = -(ly - m - logf(s));
        }
    } else {
        float inv = 1.f / s;
        float ent = 0.f;
        if (lane < C_CLS)      { float p = e0 * inv; ent -= p * log2f(fmaxf(p, 1e-8f)); }
        if (lane + 32 < C_CLS) { float p = e1 * inv; ent -= p * log2f(fmaxf(p, 1e-8f)); }
        if (lane + 64 < C_CLS) { float p = e2 * inv; ent -= p * log2f(fmaxf(p, 1e-8f)); }
        #pragma unroll
        for (int o = 16; o; o >>= 1) ent += __shfl_xor_sync(0xffffffffu, ent, o);
        if (lane == 0) g_row_ce[warp - S_SRC] = ent;
    }
}

// ---------------------------------------------------------------------------
__device__ __forceinline__ void ins5(float (&m)[5], float v) {
    if (v < m[4]) {
        if (v < m[3]) { m[4] = m[3];
            if (v < m[2]) { m[3] = m[2];
                if (v < m[1]) { m[2] = m[1];
                    if (v < m[0]) { m[1] = m[0]; m[0] = v; } else m[1] = v;
                } else m[2] = v;
            } else m[3] = v;
        } else m[4] = v;
    }
}

// Issue cp.async for one 128x256 fp16 tile (XOR-swizzled), rows [rbase, rbase+128)
__device__ __forceinline__ void load_tile(uint32_t dst_base, int rbase, int tid) {
    #pragma unroll
    for (int k = 0; k < 16; ++k) {
        int i = tid + k * 256;
        int row = i >> 5, u = i & 31;
        uint32_t sw = (uint32_t)(row * 512 + ((u ^ (row & 7)) << 4));
        CP_ASYNC16(dst_base + sw, (const char*)g_h16 + (size_t)(rbase + row) * 512 + (size_t)u * 16);
    }
}

// ---------------------------------------------------------------------------
// Persistent symmetric-tile HMMA Gram + dual-scan 5-min kernel.
// 148 CTAs, each owns a contiguous chunk of ~14 upper-triangle tiles.
// Next tile's A/B prefetched (cp.async) during the epilogue scans.
// ---------------------------------------------------------------------------
__global__ __launch_bounds__(256, 1) void dist_mma_kernel() {
    extern __shared__ char dsm_raw[];
    uint32_t raw = smem_to_u32(dsm_raw);
    uint32_t sb = (raw + 1023u) & ~1023u;
    char* dsm = dsm_raw + (sb - raw);
    float* Dsm = (float*)(dsm + OFF_D);
    float* sqI = (float*)(dsm + OFF_SQI);
    float* sqJ = (float*)(dsm + OFF_SQJ);

    int tid = threadIdx.x;
    int lane = tid & 31, wid = tid >> 5;
    int wm = wid >> 1, wn = wid & 1;

    // chunk assignment: 2080 = 8*15 + 140*14
    int c = blockIdx.x;
    int ntile = 14 + (c < 8 ? 1 : 0);
    int t0 = c * 14 + (c < 8 ? c : 8);

    // decode first tile (I, J>=I)
    int I = 0, rem = t0;
    while (rem >= NT - I) { rem -= NT - I; ++I; }
    int J = I + rem;

    // constant ldmatrix pieces
    uint32_t a_base[2];
    #pragma unroll
    for (int mi = 0; mi < 2; ++mi)
        a_base[mi] = sb + OFF_A + (uint32_t)((wm * 32 + mi * 16 + (lane & 15)) * 512);
    uint32_t b_row_off[4];
    #pragma unroll
    for (int g = 0; g < 4; ++g)
        b_row_off[g] = (uint32_t)((wn * 64 + g * 16 + (lane & 15)) * 512);
    int sxor = (lane & 15) & 7;
    int klane = lane >> 4;

    // initial load
    load_tile(sb + OFF_A, I * 128, tid);
    if (J != I) load_tile(sb + OFF_Bt, J * 128, tid);
    CP_COMMIT();

    for (int t = 0; t < ntile; ++t) {
        int rI = I * 128, rJ = J * 128;
        CP_WAIT0();
        if (tid < 128) sqI[tid] = g_sq[rI + tid];
        else           sqJ[tid - 128] = g_sq[rJ + tid - 128];
        __syncthreads();                 // tiles + sq visible

        uint32_t offB = (I == J) ? (uint32_t)OFF_A : (uint32_t)OFF_Bt;

        float acc[2][8][4];
        #pragma unroll
        for (int mi = 0; mi < 2; ++mi)
            #pragma unroll
            for (int ni = 0; ni < 8; ++ni)
                #pragma unroll
                for (int e = 0; e < 4; ++e) acc[mi][ni][e] = 0.f;

        // barrier-free k-loop: 16 chunks of k16
        #pragma unroll 4
        for (int ks = 0; ks < 16; ++ks) {
            uint32_t au = (uint32_t)(((2 * ks + klane) ^ sxor) << 4);
            uint32_t ah[2][4], bh[4][4];
            LDSM4(ah[0], a_base[0] + au);
            LDSM4(ah[1], a_base[1] + au);
            #pragma unroll
            for (int g = 0; g < 4; ++g) LDSM4(bh[g], sb + offB + b_row_off[g] + au);
            #pragma unroll
            for (int ni = 0; ni < 8; ++ni) {
                int g = ni >> 1, w = ni & 1;
                MMA16816(acc[0][ni], ah[0], bh[g][w], bh[g][w + 2]);
                MMA16816(acc[1][ni], ah[1], bh[g][w], bh[g][w + 2]);
            }
        }

        // stage raw dots to SMEM [row][col], pad 129
        #pragma unroll
        for (int mi = 0; mi < 2; ++mi)
            #pragma unroll
            for (int ni = 0; ni < 8; ++ni)
                #pragma unroll
                for (int e = 0; e < 4; ++e) {
                    int row = wm * 32 + mi * 16 + (lane >> 2) + (e >> 1) * 8;
                    int col = wn * 64 + ni * 8 + (lane & 3) * 2 + (e & 1);
                    Dsm[row * 129 + col] = acc[mi][ni][e];
                }
        __syncthreads();                 // Dsm ready; all warps done with A/B

        // prefetch next tile (overwrites A/B, now dead) — overlaps the scans
        int nI = I, nJ = J + 1;
        if (nJ == NT) { nI = I + 1; nJ = nI; }
        if (t + 1 < ntile) {
            if (nI != I) load_tile(sb + OFF_A, nI * 128, tid);
            if (nJ != nI) load_tile(sb + OFF_Bt, nJ * 128, tid);
        }
        CP_COMMIT();

        if (tid < 128) {
            // row scan: row (rI+tid) vs cols of J
            float sqi = sqI[tid];
            float s[5] = {3.4e38f, 3.4e38f, 3.4e38f, 3.4e38f, 3.4e38f};
            const float* drow = Dsm + tid * 129;
            for (int cc = 0; cc < 128; ++cc)
                ins5(s, fmaxf(fmaf(-2.f, drow[cc], sqi + sqJ[cc]), 0.f));
            float* dst = g_part + (((size_t)(J >> 5) * N_ALL + rI + tid) * 32 + (J & 31)) * 5;
            #pragma unroll
            for (int p = 0; p < 5; ++p) dst[p] = s[p];
        } else if (I != J) {
            // col scan: row (rJ+cc) vs cols of I (transposed view)
            int cc = tid - 128;
            float sqj = sqJ[cc];
            float s[5] = {3.4e38f, 3.4e38f, 3.4e38f, 3.4e38f, 3.4e38f};
            const float* dcol = Dsm + cc;
            for (int r = 0; r < 128; ++r)
                ins5(s, fmaxf(fmaf(-2.f, dcol[r * 129], sqj + sqI[r]), 0.f));
            float* dst = g_part + (((size_t)(I >> 5) * N_ALL + rJ + cc) * 32 + (I & 31)) * 5;
            #pragma unroll
            for (int p = 0; p < 5; ++p) dst[p] = s[p];
        }
        __syncthreads();                 // protect sq/Dsm before next iteration
        I = nI; J = nJ;
    }
}

// ---------------------------------------------------------------------------
// Merge 32 per-coltile partials per (half,row): one warp per row,
// lane = coltile, 5x shfl_xor butterfly of sorted 5-lists.
// ---------------------------------------------------------------------------
__global__ void merge_kernel() {
    int gw = (blockIdx.x * blockDim.x + threadIdx.x) >> 5;   // 0..16383
    int lane = threadIdx.x & 31;
    if (gw >= 2 * N_ALL) return;
    const float* p = g_part + (size_t)gw * 160 + lane * 5;
    float s[5];
    #pragma unroll
    for (int q = 0; q < 5; ++q) s[q] = p[q];                 // sorted ascending
    #pragma unroll
    for (int off = 16; off; off >>= 1) {
        float tv[5];
        #pragma unroll
        for (int q = 0; q < 5; ++q) tv[q] = __shfl_xor_sync(0xffffffffu, s[q], off);
        #pragma unroll
        for (int q = 0; q < 5; ++q) ins5(s, tv[q]);
    }
    if (lane == 0) {
        int h = gw >> 13, r = gw & (N_ALL - 1);
        // intra half: diag (~0, fp16 eps, clamped) occupies s[0];
        // dmin = s[1]; 5th smallest incl diag = s[4] (matches reference top_k)
        bool intra = ((r < S_SRC) == (h == 0));
        float dmin2 = intra ? s[1] : s[0];
        float kth2 = s[4];
        g_simh[h * N_ALL + r] = expf(-sqrtf(dmin2) / (2.f * (sqrtf(kth2) + 1e-8f)));
    }
}

// ---------------------------------------------------------------------------
// Deterministic final reduction: one block per output
// ---------------------------------------------------------------------------
__global__ void reduce_kernel(float* __restrict__ out) {
    __shared__ float sh[1024];
    int b = blockIdx.x, t = threadIdx.x;
    float a = 0.f;
    if (b == 0)      { for (int i = t; i < S_SRC; i += 1024) a += g_row_cl[i]; }
    else if (b == 1) { for (int i = t; i < S_SRC; i += 1024) a += g_row_ce[i]; }
    else             { for (int i = t; i < N_ALL; i += 1024) a += fabsf(g_simh[i] - g_simh[N_ALL + i]); }
    sh[t] = a; __syncthreads();
    for (int o = 512; o; o >>= 1) { if (t < o) sh[t] += sh[t + o]; __syncthreads(); }
    if (t == 0) out[b] = sh[0] / (float)S_SRC;
}

// ---------------------------------------------------------------------------
extern "C" void kernel_launch(void* const* d_in, const int* in_sizes, int n_in,
                              void* d_out, int out_size) {
    const float* F = (const float*)d_in[0];   // Feature_all [8192,256] f32
    const float* L = (const float*)d_in[1];   // logit_all   [8192,65]  f32
    const int*   y = (const int*)d_in[2];     // y_source    [4096]     i32
    float* out = (float*)d_out;

    cudaFuncSetAttribute(dist_mma_kernel, cudaFuncAttributeMaxDynamicSharedMemorySize, SMEM_ALLOC);

    prep_kernel<<<N_ALL / 8, 256>>>(F);       // sq norms (fp32) + fp16 image, fused
    logit_kernel<<<N_ALL / 8, 256>>>(L, y);
    dist_mma_kernel<<<NCTA, 256, SMEM_ALLOC>>>();
    merge_kernel<<<2 * N_ALL * 32 / 256, 256>>>();
    reduce_kernel<<<3, 1024>>>(out);
}

// round 13
// speedup vs baseline: 10.9945x; 1.0076x over previous
#include <cuda_runtime.h>
#include <cuda_fp16.h>
#include <math.h>
#include <stdint.h>

#define N_ALL 8192
#define D_FEAT 256
#define S_SRC 4096
#define C_CLS 65
#define NT 64                    // 128-row tiles per dim
#define NTILES 2080              // NT*(NT+1)/2
#define NCTA 148

// SMEM layout (relative to 1024-aligned base)
#define OFF_A   0                // A fp16 128x256 swizzled, 65536 B
#define OFF_Bt  65536            // B fp16 128x256 swizzled, 65536 B
#define OFF_D   131072           // dot buffer fp32 128x129 = 66048 B
#define OFF_SQI 197120           // 128 f32
#define OFF_SQJ 197632           // 128 f32
#define SMEM_BYTES 198144
#define SMEM_ALLOC (SMEM_BYTES + 1024)

// ---------------------------------------------------------------------------
// Scratch (__device__ globals: allocation-free rule)
// ---------------------------------------------------------------------------
__device__ float g_sq[N_ALL];
__device__ float g_row_cl[S_SRC];
__device__ float g_row_ce[S_SRC];
__device__ float g_simh[2 * N_ALL];
// layout: [half*N_ALL + row][q 0..4][coltile 0..31]  (coalesced merge reads)
__device__ float g_part[2 * N_ALL * 5 * 32];
__device__ __align__(16) __half g_h16[N_ALL * D_FEAT];

// ---------------------------------------------------------------------------
// PTX helpers (baseline PTX only)
// ---------------------------------------------------------------------------
__device__ __forceinline__ uint32_t smem_to_u32(const void* p) {
    uint32_t a;
    asm("{ .reg .u64 t; cvta.to.shared.u64 t, %1; cvt.u32.u64 %0, t; }" : "=r"(a) : "l"(p));
    return a;
}

#define CP_ASYNC16(DST, SRC) \
    asm volatile("cp.async.cg.shared.global [%0], [%1], 16;" :: "r"(DST), "l"(SRC) : "memory")
#define CP_COMMIT() asm volatile("cp.async.commit_group;" ::: "memory")
#define CP_WAIT0()  asm volatile("cp.async.wait_group 0;" ::: "memory")

#define LDSM4(R, ADDR) \
    asm volatile("ldmatrix.sync.aligned.m8n8.x4.shared.b16 {%0,%1,%2,%3}, [%4];" \
        : "=r"((R)[0]), "=r"((R)[1]), "=r"((R)[2]), "=r"((R)[3]) : "r"(ADDR))

#define MMA16816(D, A, B0, B1) \
    asm volatile("mma.sync.aligned.m16n8k16.row.col.f32.f16.f16.f32 " \
        "{%0,%1,%2,%3}, {%4,%5,%6,%7}, {%8,%9}, {%0,%1,%2,%3};" \
        : "+f"((D)[0]), "+f"((D)[1]), "+f"((D)[2]), "+f"((D)[3]) \
        : "r"((A)[0]), "r"((A)[1]), "r"((A)[2]), "r"((A)[3]), "r"(B0), "r"(B1))

// ---------------------------------------------------------------------------
// Fused: row squared norms (fp32, exact) + f32 -> fp16 image, over a row range
// (split into two launches so dist_mma is the 4th kernel -> ncu profiles it)
// ---------------------------------------------------------------------------
__global__ void prep_kernel(const float* __restrict__ F, int row0) {
    int row = row0 + ((blockIdx.x * blockDim.x + threadIdx.x) >> 5);
    int lane = threadIdx.x & 31;
    const float4* src = (const float4*)(F + (size_t)row * D_FEAT);
    float s = 0.f;
    #pragma unroll
    for (int i = 0; i < 2; ++i) {
        int idx = lane + 32 * i;
        float4 v = src[idx];
        s += v.x * v.x + v.y * v.y + v.z * v.z + v.w * v.w;
        __half h0 = __float2half(v.x), h1 = __float2half(v.y);
        __half h2 = __float2half(v.z), h3 = __float2half(v.w);
        uint2 ph;
        ph.x = (uint32_t)__half_as_ushort(h0) | ((uint32_t)__half_as_ushort(h1) << 16);
        ph.y = (uint32_t)__half_as_ushort(h2) | ((uint32_t)__half_as_ushort(h3) << 16);
        ((uint2*)g_h16)[(size_t)row * 64 + idx] = ph;
    }
    #pragma unroll
    for (int o = 16; o; o >>= 1) s += __shfl_xor_sync(0xffffffffu, s, o);
    if (lane == 0) g_sq[row] = s;
}

// ---------------------------------------------------------------------------
// loss_cl + loss_ce: one warp per row
// ---------------------------------------------------------------------------
__global__ void logit_kernel(const float* __restrict__ L, const int* __restrict__ y) {
    int warp = (blockIdx.x * blockDim.x + threadIdx.x) >> 5;
    int lane = threadIdx.x & 31;
    if (warp >= N_ALL) return;
    const float* row = L + (size_t)warp * C_CLS;

    float l0 = (lane < C_CLS) ? row[lane] : -3.4e38f;
    float l1 = (lane + 32 < C_CLS) ? row[lane + 32] : -3.4e38f;
    float l2 = (lane + 64 < C_CLS) ? row[lane + 64] : -3.4e38f;

    float m = fmaxf(l0, fmaxf(l1, l2));
    #pragma unroll
    for (int o = 16; o; o >>= 1) m = fmaxf(m, __shfl_xor_sync(0xffffffffu, m, o));

    float e0 = (lane < C_CLS) ? expf(l0 - m) : 0.f;
    float e1 = (lane + 32 < C_CLS) ? expf(l1 - m) : 0.f;
    float e2 = (lane + 64 < C_CLS) ? expf(l2 - m) : 0.f;
    float s = e0 + e1 + e2;
    #pragma unroll
    for (int o = 16; o; o >>= 1) s += __shfl_xor_sync(0xffffffffu, s, o);

    if (warp < S_SRC) {
        if (lane == 0) {
            float ly = row[y[warp]];
            g_row_cl[warp] = -(ly - m - logf(s));
        }
    } else {
        float inv = 1.f / s;
        float ent = 0.f;
        if (lane < C_CLS)      { float p = e0 * inv; ent -= p * log2f(fmaxf(p, 1e-8f)); }
        if (lane + 32 < C_CLS) { float p = e1 * inv; ent -= p * log2f(fmaxf(p, 1e-8f)); }
        if (lane + 64 < C_CLS) { float p = e2 * inv; ent -= p * log2f(fmaxf(p, 1e-8f)); }
        #pragma unroll
        for (int o = 16; o; o >>= 1) ent += __shfl_xor_sync(0xffffffffu, ent, o);
        if (lane == 0) g_row_ce[warp - S_SRC] = ent;
    }
}

// ---------------------------------------------------------------------------
__device__ __forceinline__ void ins5(float (&m)[5], float v) {
    if (v < m[4]) {
        if (v < m[3]) { m[4] = m[3];
            if (v < m[2]) { m[3] = m[2];
                if (v < m[1]) { m[2] = m[1];
                    if (v < m[0]) { m[1] = m[0]; m[0] = v; } else m[1] = v;
                } else m[2] = v;
            } else m[3] = v;
        } else m[4] = v;
    }
}

// Issue cp.async for one 128x256 fp16 tile (XOR-swizzled), rows [rbase, rbase+128)
__device__ __forceinline__ void load_tile(uint32_t dst_base, int rbase, int tid) {
    #pragma unroll
    for (int k = 0; k < 16; ++k) {
        int i = tid + k * 256;
        int row = i >> 5, u = i & 31;
        uint32_t sw = (uint32_t)(row * 512 + ((u ^ (row & 7)) << 4));
        CP_ASYNC16(dst_base + sw, (const char*)g_h16 + (size_t)(rbase + row) * 512 + (size_t)u * 16);
    }
}

// ---------------------------------------------------------------------------
// Persistent symmetric-tile HMMA Gram + dual-scan 5-min kernel.
// 148 CTAs, each owns a contiguous chunk of ~14 upper-triangle tiles.
// Next tile's A/B prefetched (cp.async) during the epilogue scans.
// ---------------------------------------------------------------------------
__global__ __launch_bounds__(256, 1) void dist_mma_kernel() {
    extern __shared__ char dsm_raw[];
    uint32_t raw = smem_to_u32(dsm_raw);
    uint32_t sb = (raw + 1023u) & ~1023u;
    char* dsm = dsm_raw + (sb - raw);
    float* Dsm = (float*)(dsm + OFF_D);
    float* sqI = (float*)(dsm + OFF_SQI);
    float* sqJ = (float*)(dsm + OFF_SQJ);

    int tid = threadIdx.x;
    int lane = tid & 31, wid = tid >> 5;
    int wm = wid >> 1, wn = wid & 1;

    // chunk assignment: 2080 = 8*15 + 140*14
    int c = blockIdx.x;
    int ntile = 14 + (c < 8 ? 1 : 0);
    int t0 = c * 14 + (c < 8 ? c : 8);

    // decode first tile (I, J>=I)
    int I = 0, rem = t0;
    while (rem >= NT - I) { rem -= NT - I; ++I; }
    int J = I + rem;

    // constant ldmatrix pieces
    uint32_t a_base[2];
    #pragma unroll
    for (int mi = 0; mi < 2; ++mi)
        a_base[mi] = sb + OFF_A + (uint32_t)((wm * 32 + mi * 16 + (lane & 15)) * 512);
    uint32_t b_row_off[4];
    #pragma unroll
    for (int g = 0; g < 4; ++g)
        b_row_off[g] = (uint32_t)((wn * 64 + g * 16 + (lane & 15)) * 512);
    int sxor = (lane & 15) & 7;
    int klane = lane >> 4;

    // initial load
    load_tile(sb + OFF_A, I * 128, tid);
    if (J != I) load_tile(sb + OFF_Bt, J * 128, tid);
    CP_COMMIT();

    for (int t = 0; t < ntile; ++t) {
        int rI = I * 128, rJ = J * 128;
        // sq loads are independent of cp.async — start them before the wait
        float sqv = (tid < 128) ? g_sq[rI + tid] : g_sq[rJ + tid - 128];
        CP_WAIT0();
        if (tid < 128) sqI[tid] = sqv;
        else           sqJ[tid - 128] = sqv;
        __syncthreads();                 // tiles + sq visible

        uint32_t offB = (I == J) ? (uint32_t)OFF_A : (uint32_t)OFF_Bt;

        float acc[2][8][4];
        #pragma unroll
        for (int mi = 0; mi < 2; ++mi)
            #pragma unroll
            for (int ni = 0; ni < 8; ++ni)
                #pragma unroll
                for (int e = 0; e < 4; ++e) acc[mi][ni][e] = 0.f;

        // barrier-free k-loop: 16 chunks of k16
        #pragma unroll 4
        for (int ks = 0; ks < 16; ++ks) {
            uint32_t au = (uint32_t)(((2 * ks + klane) ^ sxor) << 4);
            uint32_t ah[2][4], bh[4][4];
            LDSM4(ah[0], a_base[0] + au);
            LDSM4(ah[1], a_base[1] + au);
            #pragma unroll
            for (int g = 0; g < 4; ++g) LDSM4(bh[g], sb + offB + b_row_off[g] + au);
            #pragma unroll
            for (int ni = 0; ni < 8; ++ni) {
                int g = ni >> 1, w = ni & 1;
                MMA16816(acc[0][ni], ah[0], bh[g][w], bh[g][w + 2]);
                MMA16816(acc[1][ni], ah[1], bh[g][w], bh[g][w + 2]);
            }
        }

        // stage raw dots to SMEM [row][col], pad 129
        #pragma unroll
        for (int mi = 0; mi < 2; ++mi)
            #pragma unroll
            for (int ni = 0; ni < 8; ++ni)
                #pragma unroll
                for (int e = 0; e < 4; ++e) {
                    int row = wm * 32 + mi * 16 + (lane >> 2) + (e >> 1) * 8;
                    int col = wn * 64 + ni * 8 + (lane & 3) * 2 + (e & 1);
                    Dsm[row * 129 + col] = acc[mi][ni][e];
                }
        __syncthreads();                 // Dsm ready; all warps done with A/B

        // prefetch next tile (overwrites A/B, now dead) — overlaps the scans
        int nI = I, nJ = J + 1;
        if (nJ == NT) { nI = I + 1; nJ = nI; }
        if (t + 1 < ntile) {
            if (nI != I) load_tile(sb + OFF_A, nI * 128, tid);
            if (nJ != nI) load_tile(sb + OFF_Bt, nJ * 128, tid);
        }
        CP_COMMIT();

        if (tid < 128) {
            // row scan: row (rI+tid) vs cols of J
            float sqi = sqI[tid];
            float s[5] = {3.4e38f, 3.4e38f, 3.4e38f, 3.4e38f, 3.4e38f};
            const float* drow = Dsm + tid * 129;
            #pragma unroll 4
            for (int cc = 0; cc < 128; ++cc)
                ins5(s, fmaxf(fmaf(-2.f, drow[cc], sqi + sqJ[cc]), 0.f));
            float* dst = g_part + ((size_t)(J >> 5) * N_ALL + rI + tid) * 160 + (J & 31);
            #pragma unroll
            for (int p = 0; p < 5; ++p) dst[p * 32] = s[p];
        } else if (I != J) {
            // col scan: row (rJ+cc) vs cols of I (transposed view)
            int cc = tid - 128;
            float sqj = sqJ[cc];
            float s[5] = {3.4e38f, 3.4e38f, 3.4e38f, 3.4e38f, 3.4e38f};
            const float* dcol = Dsm + cc;
            #pragma unroll 4
            for (int r = 0; r < 128; ++r)
                ins5(s, fmaxf(fmaf(-2.f, dcol[r * 129], sqj + sqI[r]), 0.f));
            float* dst = g_part + ((size_t)(I >> 5) * N_ALL + rJ + cc) * 160 + (I & 31);
            #pragma unroll
            for (int p = 0; p < 5; ++p) dst[p * 32] = s[p];
        }
        __syncthreads();                 // protect sq/Dsm before next iteration
        I = nI; J = nJ;
    }
}

// ---------------------------------------------------------------------------
// Merge 32 per-coltile partials per (half,row): one warp per row,
// lane = coltile (coalesced reads), 5x shfl_xor butterfly of sorted 5-lists.
// ---------------------------------------------------------------------------
__global__ void merge_kernel() {
    int gw = (blockIdx.x * blockDim.x + threadIdx.x) >> 5;   // 0..16383
    int lane = threadIdx.x & 31;
    if (gw >= 2 * N_ALL) return;
    const float* p = g_part + (size_t)gw * 160 + lane;
    float s[5];
    #pragma unroll
    for (int q = 0; q < 5; ++q) s[q] = p[q * 32];            // sorted ascending
    #pragma unroll
    for (int off = 16; off; off >>= 1) {
        float tv[5];
        #pragma unroll
        for (int q = 0; q < 5; ++q) tv[q] = __shfl_xor_sync(0xffffffffu, s[q], off);
        #pragma unroll
        for (int q = 0; q < 5; ++q) ins5(s, tv[q]);
    }
    if (lane == 0) {
        int h = gw >> 13, r = gw & (N_ALL - 1);
        // intra half: diag (~0, fp16 eps, clamped) occupies s[0];
        // dmin = s[1]; 5th smallest incl diag = s[4] (matches reference top_k)
        bool intra = ((r < S_SRC) == (h == 0));
        float dmin2 = intra ? s[1] : s[0];
        float kth2 = s[4];
        g_simh[h * N_ALL + r] = expf(-sqrtf(dmin2) / (2.f * (sqrtf(kth2) + 1e-8f)));
    }
}

// ---------------------------------------------------------------------------
// Deterministic final reduction: one block per output
// ---------------------------------------------------------------------------
__global__ void reduce_kernel(float* __restrict__ out) {
    __shared__ float sh[1024];
    int b = blockIdx.x, t = threadIdx.x;
    float a = 0.f;
    if (b == 0)      { for (int i = t; i < S_SRC; i += 1024) a += g_row_cl[i]; }
    else if (b == 1) { for (int i = t; i < S_SRC; i += 1024) a += g_row_ce[i]; }
    else             { for (int i = t; i < N_ALL; i += 1024) a += fabsf(g_simh[i] - g_simh[N_ALL + i]); }
    sh[t] = a; __syncthreads();
    for (int o = 512; o; o >>= 1) { if (t < o) sh[t] += sh[t + o]; __syncthreads(); }
    if (t == 0) out[b] = sh[0] / (float)S_SRC;
}

// ---------------------------------------------------------------------------
extern "C" void kernel_launch(void* const* d_in, const int* in_sizes, int n_in,
                              void* d_out, int out_size) {
    const float* F = (const float*)d_in[0];   // Feature_all [8192,256] f32
    const float* L = (const float*)d_in[1];   // logit_all   [8192,65]  f32
    const int*   y = (const int*)d_in[2];     // y_source    [4096]     i32
    float* out = (float*)d_out;

    cudaFuncSetAttribute(dist_mma_kernel, cudaFuncAttributeMaxDynamicSharedMemorySize, SMEM_ALLOC);

    prep_kernel<<<N_ALL / 16, 256>>>(F, 0);           // rows 0..4095
    prep_kernel<<<N_ALL / 16, 256>>>(F, N_ALL / 2);   // rows 4096..8191
    logit_kernel<<<N_ALL / 8, 256>>>(L, y);
    dist_mma_kernel<<<NCTA, 256, SMEM_ALLOC>>>();     // 4th launch -> ncu captures this
    merge_kernel<<<2 * N_ALL * 32 / 256, 256>>>();
    reduce_kernel<<<3, 1024>>>(out);
}

// round 15
// speedup vs baseline: 13.3317x; 1.2126x over previous
#include <cuda_runtime.h>
#include <cuda_fp16.h>
#include <math.h>
#include <stdint.h>

#define N_ALL 8192
#define D_FEAT 256
#define S_SRC 4096
#define C_CLS 65
#define NT 64                    // 128-row tiles per dim
#define NTILES 2080              // NT*(NT+1)/2
#define NCTA 148
#define NTHR 512

// SMEM layout (relative to 1024-aligned base)
#define OFF_A   0                // A fp16 128x256 swizzled, 65536 B
#define OFF_Bt  65536            // B fp16 128x256 swizzled, 65536 B
#define OFF_D   131072           // dot buffer fp32 128x129 = 66048 B
#define OFF_SQI 197120           // 128 f32
#define OFF_SQJ 197632           // 128 f32
#define SMEM_BYTES 198144
#define SMEM_ALLOC (SMEM_BYTES + 1024)

// ---------------------------------------------------------------------------
// Scratch (__device__ globals: allocation-free rule)
// ---------------------------------------------------------------------------
__device__ float g_sq[N_ALL];
__device__ float g_row_cl[S_SRC];
__device__ float g_row_ce[S_SRC];
__device__ float g_simh[2 * N_ALL];
// layout: [half*N_ALL + row][q 0..4][coltile 0..31]  (coalesced merge reads)
__device__ float g_part[2 * N_ALL * 5 * 32];
__device__ __align__(16) __half g_h16[N_ALL * D_FEAT];

// ---------------------------------------------------------------------------
// PTX helpers (baseline PTX only)
// ---------------------------------------------------------------------------
__device__ __forceinline__ uint32_t smem_to_u32(const void* p) {
    uint32_t a;
    asm("{ .reg .u64 t; cvta.to.shared.u64 t, %1; cvt.u32.u64 %0, t; }" : "=r"(a) : "l"(p));
    return a;
}

#define CP_ASYNC16(DST, SRC) \
    asm volatile("cp.async.cg.shared.global [%0], [%1], 16;" :: "r"(DST), "l"(SRC) : "memory")
#define CP_COMMIT() asm volatile("cp.async.commit_group;" ::: "memory")
#define CP_WAIT0()  asm volatile("cp.async.wait_group 0;" ::: "memory")

#define LDSM4(R, ADDR) \
    asm volatile("ldmatrix.sync.aligned.m8n8.x4.shared.b16 {%0,%1,%2,%3}, [%4];" \
        : "=r"((R)[0]), "=r"((R)[1]), "=r"((R)[2]), "=r"((R)[3]) : "r"(ADDR))

#define MMA16816(D, A, B0, B1) \
    asm volatile("mma.sync.aligned.m16n8k16.row.col.f32.f16.f16.f32 " \
        "{%0,%1,%2,%3}, {%4,%5,%6,%7}, {%8,%9}, {%0,%1,%2,%3};" \
        : "+f"((D)[0]), "+f"((D)[1]), "+f"((D)[2]), "+f"((D)[3]) \
        : "r"((A)[0]), "r"((A)[1]), "r"((A)[2]), "r"((A)[3]), "r"(B0), "r"(B1))

// ---------------------------------------------------------------------------
// Fused: row squared norms (fp32, exact) + f32 -> fp16 image, over a row range
// (two launches so dist_mma is the 4th kernel -> ncu profiles it)
// ---------------------------------------------------------------------------
__global__ void prep_kernel(const float* __restrict__ F, int row0) {
    int row = row0 + ((blockIdx.x * blockDim.x + threadIdx.x) >> 5);
    int lane = threadIdx.x & 31;
    const float4* src = (const float4*)(F + (size_t)row * D_FEAT);
    float s = 0.f;
    #pragma unroll
    for (int i = 0; i < 2; ++i) {
        int idx = lane + 32 * i;
        float4 v = src[idx];
        s += v.x * v.x + v.y * v.y + v.z * v.z + v.w * v.w;
        __half h0 = __float2half(v.x), h1 = __float2half(v.y);
        __half h2 = __float2half(v.z), h3 = __float2half(v.w);
        uint2 ph;
        ph.x = (uint32_t)__half_as_ushort(h0) | ((uint32_t)__half_as_ushort(h1) << 16);
        ph.y = (uint32_t)__half_as_ushort(h2) | ((uint32_t)__half_as_ushort(h3) << 16);
        ((uint2*)g_h16)[(size_t)row * 64 + idx] = ph;
    }
    #pragma unroll
    for (int o = 16; o; o >>= 1) s += __shfl_xor_sync(0xffffffffu, s, o);
    if (lane == 0) g_sq[row] = s;
}

// ---------------------------------------------------------------------------
// loss_cl + loss_ce: one warp per row
// ---------------------------------------------------------------------------
__global__ void logit_kernel(const float* __restrict__ L, const int* __restrict__ y) {
    int warp = (blockIdx.x * blockDim.x + threadIdx.x) >> 5;
    int lane = threadIdx.x & 31;
    if (warp >= N_ALL) return;
    const float* row = L + (size_t)warp * C_CLS;

    float l0 = (lane < C_CLS) ? row[lane] : -3.4e38f;
    float l1 = (lane + 32 < C_CLS) ? row[lane + 32] : -3.4e38f;
    float l2 = (lane + 64 < C_CLS) ? row[lane + 64] : -3.4e38f;

    float m = fmaxf(l0, fmaxf(l1, l2));
    #pragma unroll
    for (int o = 16; o; o >>= 1) m = fmaxf(m, __shfl_xor_sync(0xffffffffu, m, o));

    float e0 = (lane < C_CLS) ? expf(l0 - m) : 0.f;
    float e1 = (lane + 32 < C_CLS) ? expf(l1 - m) : 0.f;
    float e2 = (lane + 64 < C_CLS) ? expf(l2 - m) : 0.f;
    float s = e0 + e1 + e2;
    #pragma unroll
    for (int o = 16; o; o >>= 1) s += __shfl_xor_sync(0xffffffffu, s, o);

    if (warp < S_SRC) {
        if (lane == 0) {
            float ly = row[y[warp]];
            g_row_cl[warp] = -(ly - m - logf(s));
        }
    } else {
        float inv = 1.f / s;
        float ent = 0.f;
        if (lane < C_CLS)      { float p = e0 * inv; ent -= p * log2f(fmaxf(p, 1e-8f)); }
        if (lane + 32 < C_CLS) { float p = e1 * inv; ent -= p * log2f(fmaxf(p, 1e-8f)); }
        if (lane + 64 < C_CLS) { float p = e2 * inv; ent -= p * log2f(fmaxf(p, 1e-8f)); }
        #pragma unroll
        for (int o = 16; o; o >>= 1) ent += __shfl_xor_sync(0xffffffffu, ent, o);
        if (lane == 0) g_row_ce[warp - S_SRC] = ent;
    }
}

// ---------------------------------------------------------------------------
__device__ __forceinline__ void ins5(float (&m)[5], float v) {
    if (v < m[4]) {
        if (v < m[3]) { m[4] = m[3];
            if (v < m[2]) { m[3] = m[2];
                if (v < m[1]) { m[2] = m[1];
                    if (v < m[0]) { m[1] = m[0]; m[0] = v; } else m[1] = v;
                } else m[2] = v;
            } else m[3] = v;
        } else m[4] = v;
    }
}

// Issue cp.async for one 128x256 fp16 tile (XOR-swizzled), rows [rbase, rbase+128)
__device__ __forceinline__ void load_tile(uint32_t dst_base, int rbase, int tid) {
    #pragma unroll
    for (int k = 0; k < 8; ++k) {
        int i = tid + k * NTHR;
        int row = i >> 5, u = i & 31;
        uint32_t sw = (uint32_t)(row * 512 + ((u ^ (row & 7)) << 4));
        CP_ASYNC16(dst_base + sw, (const char*)g_h16 + (size_t)(rbase + row) * 512 + (size_t)u * 16);
    }
}

// ---------------------------------------------------------------------------
// Persistent symmetric-tile HMMA Gram + dual-scan 5-min kernel.
// 148 CTAs x 512 threads (16 warps: 4m x 4n, warp tile 32x32).
// Epilogue scans split 2 threads per row/col, merged via buffered shfl_xor(1).
// ---------------------------------------------------------------------------
__global__ __launch_bounds__(NTHR, 1) void dist_mma_kernel() {
    extern __shared__ char dsm_raw[];
    uint32_t raw = smem_to_u32(dsm_raw);
    uint32_t sb = (raw + 1023u) & ~1023u;
    char* dsm = dsm_raw + (sb - raw);
    float* Dsm = (float*)(dsm + OFF_D);
    float* sqI = (float*)(dsm + OFF_SQI);
    float* sqJ = (float*)(dsm + OFF_SQJ);

    int tid = threadIdx.x;
    int lane = tid & 31, wid = tid >> 5;
    int wm = wid >> 2, wn = wid & 3;

    // chunk assignment: 2080 = 8*15 + 140*14
    int c = blockIdx.x;
    int ntile = 14 + (c < 8 ? 1 : 0);
    int t0 = c * 14 + (c < 8 ? c : 8);

    // decode first tile (I, J>=I)
    int I = 0, rem = t0;
    while (rem >= NT - I) { rem -= NT - I; ++I; }
    int J = I + rem;

    // constant ldmatrix pieces
    uint32_t a_base[2];
    #pragma unroll
    for (int mi = 0; mi < 2; ++mi)
        a_base[mi] = sb + OFF_A + (uint32_t)((wm * 32 + mi * 16 + (lane & 15)) * 512);
    uint32_t b_row_off[2];
    #pragma unroll
    for (int g = 0; g < 2; ++g)
        b_row_off[g] = (uint32_t)((wn * 32 + g * 16 + (lane & 15)) * 512);
    int sxor = (lane & 15) & 7;
    int klane = lane >> 4;

    // initial load
    load_tile(sb + OFF_A, I * 128, tid);
    if (J != I) load_tile(sb + OFF_Bt, J * 128, tid);
    CP_COMMIT();

    for (int t = 0; t < ntile; ++t) {
        int rI = I * 128, rJ = J * 128;
        // sq loads are independent of cp.async — start them before the wait
        float sqv = 0.f;
        if (tid < 128) sqv = g_sq[rI + tid];
        else if (tid < 256) sqv = g_sq[rJ + tid - 128];
        CP_WAIT0();
        if (tid < 128) sqI[tid] = sqv;
        else if (tid < 256) sqJ[tid - 128] = sqv;
        __syncthreads();                 // tiles + sq visible

        uint32_t offB = (I == J) ? (uint32_t)OFF_A : (uint32_t)OFF_Bt;

        float acc[2][4][4];
        #pragma unroll
        for (int mi = 0; mi < 2; ++mi)
            #pragma unroll
            for (int ni = 0; ni < 4; ++ni)
                #pragma unroll
                for (int e = 0; e < 4; ++e) acc[mi][ni][e] = 0.f;

        // barrier-free k-loop: 16 chunks of k16 (4 LDSM + 8 MMA per warp)
        #pragma unroll 4
        for (int ks = 0; ks < 16; ++ks) {
            uint32_t au = (uint32_t)(((2 * ks + klane) ^ sxor) << 4);
            uint32_t ah[2][4], bh[2][4];
            LDSM4(ah[0], a_base[0] + au);
            LDSM4(ah[1], a_base[1] + au);
            LDSM4(bh[0], sb + offB + b_row_off[0] + au);
            LDSM4(bh[1], sb + offB + b_row_off[1] + au);
            #pragma unroll
            for (int ni = 0; ni < 4; ++ni) {
                int g = ni >> 1, w = ni & 1;
                MMA16816(acc[0][ni], ah[0], bh[g][w], bh[g][w + 2]);
                MMA16816(acc[1][ni], ah[1], bh[g][w], bh[g][w + 2]);
            }
        }

        // stage raw dots to SMEM [row][col], pad 129
        #pragma unroll
        for (int mi = 0; mi < 2; ++mi)
            #pragma unroll
            for (int ni = 0; ni < 4; ++ni)
                #pragma unroll
                for (int e = 0; e < 4; ++e) {
                    int row = wm * 32 + mi * 16 + (lane >> 2) + (e >> 1) * 8;
                    int col = wn * 32 + ni * 8 + (lane & 3) * 2 + (e & 1);
                    Dsm[row * 129 + col] = acc[mi][ni][e];
                }
        __syncthreads();                 // Dsm ready; all warps done with A/B

        // prefetch next tile (overwrites A/B, now dead) — overlaps the scans
        int nI = I, nJ = J + 1;
        if (nJ == NT) { nI = I + 1; nJ = nI; }
        if (t + 1 < ntile) {
            if (nI != I) load_tile(sb + OFF_A, nI * 128, tid);
            if (nJ != nI) load_tile(sb + OFF_Bt, nJ * 128, tid);
        }
        CP_COMMIT();

        // dual scans, 2 threads per row/col (64 elems each);
        // pair-merge buffers the partner's full sorted list BEFORE inserting
        if (tid < 256) {
            // row scan: row (rI + tid/2) vs cols of J
            int r = tid >> 1, hf = tid & 1;
            float sqi = sqI[r];
            float s[5] = {3.4e38f, 3.4e38f, 3.4e38f, 3.4e38f, 3.4e38f};
            const float* drow = Dsm + r * 129 + hf * 64;
            const float* sqc = sqJ + hf * 64;
            #pragma unroll 4
            for (int cc = 0; cc < 64; ++cc)
                ins5(s, fmaxf(fmaf(-2.f, drow[cc], sqi + sqc[cc]), 0.f));
            float tv[5];
            #pragma unroll
            for (int q = 0; q < 5; ++q) tv[q] = __shfl_xor_sync(0xffffffffu, s[q], 1);
            #pragma unroll
            for (int q = 0; q < 5; ++q) ins5(s, tv[q]);
            if (hf == 0) {
                float* dst = g_part + ((size_t)(J >> 5) * N_ALL + rI + r) * 160 + (J & 31);
                #pragma unroll
                for (int p = 0; p < 5; ++p) dst[p * 32] = s[p];
            }
        } else if (I != J) {
            // col scan: row (rJ + cc) vs cols of I (transposed view)
            int cc = (tid - 256) >> 1, hf = tid & 1;
            float sqj = sqJ[cc];
            float s[5] = {3.4e38f, 3.4e38f, 3.4e38f, 3.4e38f, 3.4e38f};
            const float* dcol = Dsm + cc + (size_t)hf * 64 * 129;
            const float* sqr = sqI + hf * 64;
            #pragma unroll 4
            for (int r = 0; r < 64; ++r)
                ins5(s, fmaxf(fmaf(-2.f, dcol[r * 129], sqj + sqr[r]), 0.f));
            float tv[5];
            #pragma unroll
            for (int q = 0; q < 5; ++q) tv[q] = __shfl_xor_sync(0xffffffffu, s[q], 1);
            #pragma unroll
            for (int q = 0; q < 5; ++q) ins5(s, tv[q]);
            if (hf == 0) {
                float* dst = g_part + ((size_t)(I >> 5) * N_ALL + rJ + cc) * 160 + (I & 31);
                #pragma unroll
                for (int p = 0; p < 5; ++p) dst[p * 32] = s[p];
            }
        }
        __syncthreads();                 // protect sq/Dsm before next iteration
        I = nI; J = nJ;
    }
}

// ---------------------------------------------------------------------------
// Merge 32 per-coltile partials per (half,row): one warp per row,
// lane = coltile (coalesced reads), 5x shfl_xor butterfly of sorted 5-lists.
// ---------------------------------------------------------------------------
__global__ void merge_kernel() {
    int gw = (blockIdx.x * blockDim.x + threadIdx.x) >> 5;   // 0..16383
    int lane = threadIdx.x & 31;
    if (gw >= 2 * N_ALL) return;
    const float* p = g_part + (size_t)gw * 160 + lane;
    float s[5];
    #pragma unroll
    for (int q = 0; q < 5; ++q) s[q] = p[q * 32];            // sorted ascending
    #pragma unroll
    for (int off = 16; off; off >>= 1) {
        float tv[5];
        #pragma unroll
        for (int q = 0; q < 5; ++q) tv[q] = __shfl_xor_sync(0xffffffffu, s[q], off);
        #pragma unroll
        for (int q = 0; q < 5; ++q) ins5(s, tv[q]);
    }
    if (lane == 0) {
        int h = gw >> 13, r = gw & (N_ALL - 1);
        // intra half: diag (~0, fp16 eps, clamped) occupies s[0];
        // dmin = s[1]; 5th smallest incl diag = s[4] (matches reference top_k)
        bool intra = ((r < S_SRC) == (h == 0));
        float dmin2 = intra ? s[1] : s[0];
        float kth2 = s[4];
        g_simh[h * N_ALL + r] = expf(-sqrtf(dmin2) / (2.f * (sqrtf(kth2) + 1e-8f)));
    }
}

// ---------------------------------------------------------------------------
// Deterministic final reduction: one block per output
// ---------------------------------------------------------------------------
__global__ void reduce_kernel(float* __restrict__ out) {
    __shared__ float sh[1024];
    int b = blockIdx.x, t = threadIdx.x;
    float a = 0.f;
    if (b == 0)      { for (int i = t; i < S_SRC; i += 1024) a += g_row_cl[i]; }
    else if (b == 1) { for (int i = t; i < S_SRC; i += 1024) a += g_row_ce[i]; }
    else             { for (int i = t; i < N_ALL; i += 1024) a += fabsf(g_simh[i] - g_simh[N_ALL + i]); }
    sh[t] = a; __syncthreads();
    for (int o = 512; o; o >>= 1) { if (t < o) sh[t] += sh[t + o]; __syncthreads(); }
    if (t == 0) out[b] = sh[0] / (float)S_SRC;
}

// ---------------------------------------------------------------------------
extern "C" void kernel_launch(void* const* d_in, const int* in_sizes, int n_in,
                              void* d_out, int out_size) {
    const float* F = (const float*)d_in[0];   // Feature_all [8192,256] f32
    const float* L = (const float*)d_in[1];   // logit_all   [8192,65]  f32
    const int*   y = (const int*)d_in[2];     // y_source    [4096]     i32
    float* out = (float*)d_out;

    cudaFuncSetAttribute(dist_mma_kernel, cudaFuncAttributeMaxDynamicSharedMemorySize, SMEM_ALLOC);

    prep_kernel<<<N_ALL / 16, 256>>>(F, 0);           // rows 0..4095
    prep_kernel<<<N_ALL / 16, 256>>>(F, N_ALL / 2);   // rows 4096..8191
    logit_kernel<<<N_ALL / 8, 256>>>(L, y);
    dist_mma_kernel<<<NCTA, NTHR, SMEM_ALLOC>>>();    // 4th launch -> ncu captures this
    merge_kernel<<<2 * N_ALL * 32 / 256, 256>>>();
    reduce_kernel<<<3, 1024>>>(out);
}

// round 16
// speedup vs baseline: 13.8489x; 1.0388x over previous
#include <cuda_runtime.h>
#include <cuda_fp16.h>
#include <math.h>
#include <stdint.h>

#define N_ALL 8192
#define D_FEAT 256
#define S_SRC 4096
#define C_CLS 65
#define NT 64                    // 128-row tiles per dim
#define NTILES 2080              // NT*(NT+1)/2
#define NCTA 148
#define NTHR 1024

// SMEM layout (relative to 1024-aligned base)
#define OFF_A   0                // A fp16 128x256 swizzled, 65536 B
#define OFF_Bt  65536            // B fp16 128x256 swizzled, 65536 B
#define OFF_D   131072           // dot buffer fp32 128x129 = 66048 B
#define OFF_SQI 197120           // 128 f32
#define OFF_SQJ 197632           // 128 f32
#define SMEM_BYTES 198144
#define SMEM_ALLOC (SMEM_BYTES + 1024)

// ---------------------------------------------------------------------------
// Scratch (__device__ globals: allocation-free rule)
// ---------------------------------------------------------------------------
__device__ float g_sq[N_ALL];
__device__ float g_row_cl[S_SRC];
__device__ float g_row_ce[S_SRC];
__device__ float g_simh[2 * N_ALL];
// layout: [half*N_ALL + row][q 0..4][coltile 0..31]  (coalesced merge reads)
__device__ float g_part[2 * N_ALL * 5 * 32];
__device__ __align__(16) __half g_h16[N_ALL * D_FEAT];

// ---------------------------------------------------------------------------
// PTX helpers (baseline PTX only)
// ---------------------------------------------------------------------------
__device__ __forceinline__ uint32_t smem_to_u32(const void* p) {
    uint32_t a;
    asm("{ .reg .u64 t; cvta.to.shared.u64 t, %1; cvt.u32.u64 %0, t; }" : "=r"(a) : "l"(p));
    return a;
}

#define CP_ASYNC16(DST, SRC) \
    asm volatile("cp.async.cg.shared.global [%0], [%1], 16;" :: "r"(DST), "l"(SRC) : "memory")
#define CP_COMMIT() asm volatile("cp.async.commit_group;" ::: "memory")
#define CP_WAIT0()  asm volatile("cp.async.wait_group 0;" ::: "memory")

#define LDSM4(R, ADDR) \
    asm volatile("ldmatrix.sync.aligned.m8n8.x4.shared.b16 {%0,%1,%2,%3}, [%4];" \
        : "=r"((R)[0]), "=r"((R)[1]), "=r"((R)[2]), "=r"((R)[3]) : "r"(ADDR))

#define MMA16816(D, A, B0, B1) \
    asm volatile("mma.sync.aligned.m16n8k16.row.col.f32.f16.f16.f32 " \
        "{%0,%1,%2,%3}, {%4,%5,%6,%7}, {%8,%9}, {%0,%1,%2,%3};" \
        : "+f"((D)[0]), "+f"((D)[1]), "+f"((D)[2]), "+f"((D)[3]) \
        : "r"((A)[0]), "r"((A)[1]), "r"((A)[2]), "r"((A)[3]), "r"(B0), "r"(B1))

// ---------------------------------------------------------------------------
// Fused: row squared norms (fp32, exact) + f32 -> fp16 image, over a row range
// (two launches so dist_mma is the 4th kernel -> ncu profiles it)
// ---------------------------------------------------------------------------
__global__ void prep_kernel(const float* __restrict__ F, int row0) {
    int row = row0 + ((blockIdx.x * blockDim.x + threadIdx.x) >> 5);
    int lane = threadIdx.x & 31;
    const float4* src = (const float4*)(F + (size_t)row * D_FEAT);
    float s = 0.f;
    #pragma unroll
    for (int i = 0; i < 2; ++i) {
        int idx = lane + 32 * i;
        float4 v = src[idx];
        s += v.x * v.x + v.y * v.y + v.z * v.z + v.w * v.w;
        __half h0 = __float2half(v.x), h1 = __float2half(v.y);
        __half h2 = __float2half(v.z), h3 = __float2half(v.w);
        uint2 ph;
        ph.x = (uint32_t)__half_as_ushort(h0) | ((uint32_t)__half_as_ushort(h1) << 16);
        ph.y = (uint32_t)__half_as_ushort(h2) | ((uint32_t)__half_as_ushort(h3) << 16);
        ((uint2*)g_h16)[(size_t)row * 64 + idx] = ph;
    }
    #pragma unroll
    for (int o = 16; o; o >>= 1) s += __shfl_xor_sync(0xffffffffu, s, o);
    if (lane == 0) g_sq[row] = s;
}

// ---------------------------------------------------------------------------
// loss_cl + loss_ce: one warp per row
// ---------------------------------------------------------------------------
__global__ void logit_kernel(const float* __restrict__ L, const int* __restrict__ y) {
    int warp = (blockIdx.x * blockDim.x + threadIdx.x) >> 5;
    int lane = threadIdx.x & 31;
    if (warp >= N_ALL) return;
    const float* row = L + (size_t)warp * C_CLS;

    float l0 = (lane < C_CLS) ? row[lane] : -3.4e38f;
    float l1 = (lane + 32 < C_CLS) ? row[lane + 32] : -3.4e38f;
    float l2 = (lane + 64 < C_CLS) ? row[lane + 64] : -3.4e38f;

    float m = fmaxf(l0, fmaxf(l1, l2));
    #pragma unroll
    for (int o = 16; o; o >>= 1) m = fmaxf(m, __shfl_xor_sync(0xffffffffu, m, o));

    float e0 = (lane < C_CLS) ? expf(l0 - m) : 0.f;
    float e1 = (lane + 32 < C_CLS) ? expf(l1 - m) : 0.f;
    float e2 = (lane + 64 < C_CLS) ? expf(l2 - m) : 0.f;
    float s = e0 + e1 + e2;
    #pragma unroll
    for (int o = 16; o; o >>= 1) s += __shfl_xor_sync(0xffffffffu, s, o);

    if (warp < S_SRC) {
        if (lane == 0) {
            float ly = row[y[warp]];
            g_row_cl[warp] = -(ly - m - logf(s));
        }
    } else {
        float inv = 1.f / s;
        float ent = 0.f;
        if (lane < C_CLS)      { float p = e0 * inv; ent -= p * log2f(fmaxf(p, 1e-8f)); }
        if (lane + 32 < C_CLS) { float p = e1 * inv; ent -= p * log2f(fmaxf(p, 1e-8f)); }
        if (lane + 64 < C_CLS) { float p = e2 * inv; ent -= p * log2f(fmaxf(p, 1e-8f)); }
        #pragma unroll
        for (int o = 16; o; o >>= 1) ent += __shfl_xor_sync(0xffffffffu, ent, o);
        if (lane == 0) g_row_ce[warp - S_SRC] = ent;
    }
}

// ---------------------------------------------------------------------------
__device__ __forceinline__ void ins5(float (&m)[5], float v) {
    if (v < m[4]) {
        if (v < m[3]) { m[4] = m[3];
            if (v < m[2]) { m[3] = m[2];
                if (v < m[1]) { m[2] = m[1];
                    if (v < m[0]) { m[1] = m[0]; m[0] = v; } else m[1] = v;
                } else m[2] = v;
            } else m[3] = v;
        } else m[4] = v;
    }
}

// Issue cp.async for one 128x256 fp16 tile (XOR-swizzled), rows [rbase, rbase+128)
__device__ __forceinline__ void load_tile(uint32_t dst_base, int rbase, int tid) {
    #pragma unroll
    for (int k = 0; k < 4; ++k) {
        int i = tid + k * NTHR;
        int row = i >> 5, u = i & 31;
        uint32_t sw = (uint32_t)(row * 512 + ((u ^ (row & 7)) << 4));
        CP_ASYNC16(dst_base + sw, (const char*)g_h16 + (size_t)(rbase + row) * 512 + (size_t)u * 16);
    }
}

// ---------------------------------------------------------------------------
// Persistent symmetric-tile HMMA Gram + dual-scan 5-min kernel.
// 148 CTAs x 1024 threads (32 warps: 4m x 8n, warp tile 32x16 — 8 warps/SMSP
// to hide LDSM/MMA latency; R15 measured occ 25%, issue 47%).
// Epilogue scans split 4 threads per row/col, merged via buffered shfl_xor.
// ---------------------------------------------------------------------------
__global__ __launch_bounds__(NTHR, 1) void dist_mma_kernel() {
    extern __shared__ char dsm_raw[];
    uint32_t raw = smem_to_u32(dsm_raw);
    uint32_t sb = (raw + 1023u) & ~1023u;
    char* dsm = dsm_raw + (sb - raw);
    float* Dsm = (float*)(dsm + OFF_D);
    float* sqI = (float*)(dsm + OFF_SQI);
    float* sqJ = (float*)(dsm + OFF_SQJ);

    int tid = threadIdx.x;
    int lane = tid & 31, wid = tid >> 5;
    int wm = wid >> 3, wn = wid & 7;

    // chunk assignment: 2080 = 8*15 + 140*14
    int c = blockIdx.x;
    int ntile = 14 + (c < 8 ? 1 : 0);
    int t0 = c * 14 + (c < 8 ? c : 8);

    // decode first tile (I, J>=I)
    int I = 0, rem = t0;
    while (rem >= NT - I) { rem -= NT - I; ++I; }
    int J = I + rem;

    // constant ldmatrix pieces
    uint32_t a_base[2];
    #pragma unroll
    for (int mi = 0; mi < 2; ++mi)
        a_base[mi] = sb + OFF_A + (uint32_t)((wm * 32 + mi * 16 + (lane & 15)) * 512);
    uint32_t b_row_off = (uint32_t)((wn * 16 + (lane & 15)) * 512);
    int sxor = (lane & 15) & 7;
    int klane = lane >> 4;

    // initial load
    load_tile(sb + OFF_A, I * 128, tid);
    if (J != I) load_tile(sb + OFF_Bt, J * 128, tid);
    CP_COMMIT();

    for (int t = 0; t < ntile; ++t) {
        int rI = I * 128, rJ = J * 128;
        // sq loads are independent of cp.async — start them before the wait
        float sqv = 0.f;
        if (tid < 128) sqv = g_sq[rI + tid];
        else if (tid < 256) sqv = g_sq[rJ + tid - 128];
        CP_WAIT0();
        if (tid < 128) sqI[tid] = sqv;
        else if (tid < 256) sqJ[tid - 128] = sqv;
        __syncthreads();                 // tiles + sq visible

        uint32_t offB = (I == J) ? (uint32_t)OFF_A : (uint32_t)OFF_Bt;

        float acc[2][2][4];
        #pragma unroll
        for (int mi = 0; mi < 2; ++mi)
            #pragma unroll
            for (int ni = 0; ni < 2; ++ni)
                #pragma unroll
                for (int e = 0; e < 4; ++e) acc[mi][ni][e] = 0.f;

        // barrier-free k-loop: 16 chunks of k16 (3 LDSM + 4 MMA per warp)
        #pragma unroll 4
        for (int ks = 0; ks < 16; ++ks) {
            uint32_t au = (uint32_t)(((2 * ks + klane) ^ sxor) << 4);
            uint32_t ah[2][4], bh[4];
            LDSM4(ah[0], a_base[0] + au);
            LDSM4(ah[1], a_base[1] + au);
            LDSM4(bh, sb + offB + b_row_off + au);
            #pragma unroll
            for (int ni = 0; ni < 2; ++ni) {
                MMA16816(acc[0][ni], ah[0], bh[ni], bh[ni + 2]);
                MMA16816(acc[1][ni], ah[1], bh[ni], bh[ni + 2]);
            }
        }

        // stage raw dots to SMEM [row][col], pad 129
        #pragma unroll
        for (int mi = 0; mi < 2; ++mi)
            #pragma unroll
            for (int ni = 0; ni < 2; ++ni)
                #pragma unroll
                for (int e = 0; e < 4; ++e) {
                    int row = wm * 32 + mi * 16 + (lane >> 2) + (e >> 1) * 8;
                    int col = wn * 16 + ni * 8 + (lane & 3) * 2 + (e & 1);
                    Dsm[row * 129 + col] = acc[mi][ni][e];
                }
        __syncthreads();                 // Dsm ready; all warps done with A/B

        // prefetch next tile (overwrites A/B, now dead) — overlaps the scans
        int nI = I, nJ = J + 1;
        if (nJ == NT) { nI = I + 1; nJ = nI; }
        if (t + 1 < ntile) {
            if (nI != I) load_tile(sb + OFF_A, nI * 128, tid);
            if (nJ != nI) load_tile(sb + OFF_Bt, nJ * 128, tid);
        }
        CP_COMMIT();

        // dual scans, 4 threads per row/col (32 elems each);
        // pair-merge buffers the partner's full sorted list BEFORE inserting
        if (tid < 512) {
            // row scan: row (rI + tid/4) vs cols of J
            int r = tid >> 2, q = tid & 3;
            float sqi = sqI[r];
            float s[5] = {3.4e38f, 3.4e38f, 3.4e38f, 3.4e38f, 3.4e38f};
            const float* drow = Dsm + r * 129 + q * 32;
            const float* sqc = sqJ + q * 32;
            #pragma unroll 4
            for (int cc = 0; cc < 32; ++cc)
                ins5(s, fmaxf(fmaf(-2.f, drow[cc], sqi + sqc[cc]), 0.f));
            #pragma unroll
            for (int off = 1; off <= 2; off <<= 1) {
                float tv[5];
                #pragma unroll
                for (int p = 0; p < 5; ++p) tv[p] = __shfl_xor_sync(0xffffffffu, s[p], off);
                #pragma unroll
                for (int p = 0; p < 5; ++p) ins5(s, tv[p]);
            }
            if (q == 0) {
                float* dst = g_part + ((size_t)(J >> 5) * N_ALL + rI + r) * 160 + (J & 31);
                #pragma unroll
                for (int p = 0; p < 5; ++p) dst[p * 32] = s[p];
            }
        } else if (I != J) {
            // col scan: row (rJ + cc) vs cols of I (transposed view)
            int cc = (tid - 512) >> 2, q = tid & 3;
            float sqj = sqJ[cc];
            float s[5] = {3.4e38f, 3.4e38f, 3.4e38f, 3.4e38f, 3.4e38f};
            const float* dcol = Dsm + cc + (size_t)(q * 32) * 129;
            const float* sqr = sqI + q * 32;
            #pragma unroll 4
            for (int r = 0; r < 32; ++r)
                ins5(s, fmaxf(fmaf(-2.f, dcol[r * 129], sqj + sqr[r]), 0.f));
            #pragma unroll
            for (int off = 1; off <= 2; off <<= 1) {
                float tv[5];
                #pragma unroll
                for (int p = 0; p < 5; ++p) tv[p] = __shfl_xor_sync(0xffffffffu, s[p], off);
                #pragma unroll
                for (int p = 0; p < 5; ++p) ins5(s, tv[p]);
            }
            if (q == 0) {
                float* dst = g_part + ((size_t)(I >> 5) * N_ALL + rJ + cc) * 160 + (I & 31);
                #pragma unroll
                for (int p = 0; p < 5; ++p) dst[p * 32] = s[p];
            }
        }
        __syncthreads();                 // protect sq/Dsm before next iteration
        I = nI; J = nJ;
    }
}

// ---------------------------------------------------------------------------
// Merge 32 per-coltile partials per (half,row): one warp per row,
// lane = coltile (coalesced reads), 5x shfl_xor butterfly of sorted 5-lists.
// ---------------------------------------------------------------------------
__global__ void merge_kernel() {
    int gw = (blockIdx.x * blockDim.x + threadIdx.x) >> 5;   // 0..16383
    int lane = threadIdx.x & 31;
    if (gw >= 2 * N_ALL) return;
    const float* p = g_part + (size_t)gw * 160 + lane;
    float s[5];
    #pragma unroll
    for (int q = 0; q < 5; ++q) s[q] = p[q * 32];            // sorted ascending
    #pragma unroll
    for (int off = 16; off; off >>= 1) {
        float tv[5];
        #pragma unroll
        for (int q = 0; q < 5; ++q) tv[q] = __shfl_xor_sync(0xffffffffu, s[q], off);
        #pragma unroll
        for (int q = 0; q < 5; ++q) ins5(s, tv[q]);
    }
    if (lane == 0) {
        int h = gw >> 13, r = gw & (N_ALL - 1);
        // intra half: diag (~0, fp16 eps, clamped) occupies s[0];
        // dmin = s[1]; 5th smallest incl diag = s[4] (matches reference top_k)
        bool intra = ((r < S_SRC) == (h == 0));
        float dmin2 = intra ? s[1] : s[0];
        float kth2 = s[4];
        g_simh[h * N_ALL + r] = expf(-sqrtf(dmin2) / (2.f * (sqrtf(kth2) + 1e-8f)));
    }
}

// ---------------------------------------------------------------------------
// Deterministic final reduction: one block per output
// ---------------------------------------------------------------------------
__global__ void reduce_kernel(float* __restrict__ out) {
    __shared__ float sh[1024];
    int b = blockIdx.x, t = threadIdx.x;
    float a = 0.f;
    if (b == 0)      { for (int i = t; i < S_SRC; i += 1024) a += g_row_cl[i]; }
    else if (b == 1) { for (int i = t; i < S_SRC; i += 1024) a += g_row_ce[i]; }
    else             { for (int i = t; i < N_ALL; i += 1024) a += fabsf(g_simh[i] - g_simh[N_ALL + i]); }
    sh[t] = a; __syncthreads();
    for (int o = 512; o; o >>= 1) { if (t < o) sh[t] += sh[t + o]; __syncthreads(); }
    if (t == 0) out[b] = sh[0] / (float)S_SRC;
}

// ---------------------------------------------------------------------------
extern "C" void kernel_launch(void* const* d_in, const int* in_sizes, int n_in,
                              void* d_out, int out_size) {
    const float* F = (const float*)d_in[0];   // Feature_all [8192,256] f32
    const float* L = (const float*)d_in[1];   // logit_all   [8192,65]  f32
    const int*   y = (const int*)d_in[2];     // y_source    [4096]     i32
    float* out = (float*)d_out;

    cudaFuncSetAttribute(dist_mma_kernel, cudaFuncAttributeMaxDynamicSharedMemorySize, SMEM_ALLOC);

    prep_kernel<<<N_ALL / 16, 256>>>(F, 0);           // rows 0..4095
    prep_kernel<<<N_ALL / 16, 256>>>(F, N_ALL / 2);   // rows 4096..8191
    logit_kernel<<<N_ALL / 8, 256>>>(L, y);
    dist_mma_kernel<<<NCTA, NTHR, SMEM_ALLOC>>>();    // 4th launch -> ncu captures this
    merge_kernel<<<2 * N_ALL * 32 / 256, 256>>>();
    reduce_kernel<<<3, 1024>>>(out);
}

// round 17
// speedup vs baseline: 13.9981x; 1.0108x over previous
#include <cuda_runtime.h>
#include <cuda_fp16.h>
#include <math.h>
#include <stdint.h>

#define N_ALL 8192
#define D_FEAT 256
#define S_SRC 4096
#define C_CLS 65
#define NT 64                    // 128-row tiles per dim
#define NTILES 2080              // NT*(NT+1)/2
#define NCTA 148
#define NTHR 1024
#define PADD 132                 // Dsm row stride (132%32=4 -> conflict-free rotated scans)

// SMEM layout (relative to 1024-aligned base)
#define OFF_A   0                // A fp16 128x256 swizzled, 65536 B
#define OFF_Bt  65536            // B fp16 128x256 swizzled, 65536 B
#define OFF_D   131072           // dot buffer fp32 128x132 = 67584 B
#define OFF_SQI 198656           // 128 f32
#define OFF_SQJ 199168           // 128 f32
#define SMEM_BYTES 199680
#define SMEM_ALLOC (SMEM_BYTES + 1024)

// ---------------------------------------------------------------------------
// Scratch (__device__ globals: allocation-free rule)
// ---------------------------------------------------------------------------
__device__ float g_sq[N_ALL];
__device__ float g_row_cl[S_SRC];
__device__ float g_row_ce[S_SRC];
__device__ float g_simh[2 * N_ALL];
// layout: [half*N_ALL + row][q 0..4][coltile 0..31]  (coalesced merge reads)
__device__ float g_part[2 * N_ALL * 5 * 32];
__device__ __align__(16) __half g_h16[N_ALL * D_FEAT];

// ---------------------------------------------------------------------------
// PTX helpers (baseline PTX only)
// ---------------------------------------------------------------------------
__device__ __forceinline__ uint32_t smem_to_u32(const void* p) {
    uint32_t a;
    asm("{ .reg .u64 t; cvta.to.shared.u64 t, %1; cvt.u32.u64 %0, t; }" : "=r"(a) : "l"(p));
    return a;
}

#define CP_ASYNC16(DST, SRC) \
    asm volatile("cp.async.cg.shared.global [%0], [%1], 16;" :: "r"(DST), "l"(SRC) : "memory")
#define CP_COMMIT() asm volatile("cp.async.commit_group;" ::: "memory")
#define CP_WAIT0()  asm volatile("cp.async.wait_group 0;" ::: "memory")

#define LDSM4(R, ADDR) \
    asm volatile("ldmatrix.sync.aligned.m8n8.x4.shared.b16 {%0,%1,%2,%3}, [%4];" \
        : "=r"((R)[0]), "=r"((R)[1]), "=r"((R)[2]), "=r"((R)[3]) : "r"(ADDR))

#define MMA16816(D, A, B0, B1) \
    asm volatile("mma.sync.aligned.m16n8k16.row.col.f32.f16.f16.f32 " \
        "{%0,%1,%2,%3}, {%4,%5,%6,%7}, {%8,%9}, {%0,%1,%2,%3};" \
        : "+f"((D)[0]), "+f"((D)[1]), "+f"((D)[2]), "+f"((D)[3]) \
        : "r"((A)[0]), "r"((A)[1]), "r"((A)[2]), "r"((A)[3]), "r"(B0), "r"(B1))

// ---------------------------------------------------------------------------
// Fused: row squared norms (fp32, exact) + f32 -> fp16 image, over a row range
// (two launches so dist_mma is the 4th kernel -> ncu profiles it)
// ---------------------------------------------------------------------------
__global__ void prep_kernel(const float* __restrict__ F, int row0) {
    int row = row0 + ((blockIdx.x * blockDim.x + threadIdx.x) >> 5);
    int lane = threadIdx.x & 31;
    const float4* src = (const float4*)(F + (size_t)row * D_FEAT);
    float s = 0.f;
    #pragma unroll
    for (int i = 0; i < 2; ++i) {
        int idx = lane + 32 * i;
        float4 v = src[idx];
        s += v.x * v.x + v.y * v.y + v.z * v.z + v.w * v.w;
        __half h0 = __float2half(v.x), h1 = __float2half(v.y);
        __half h2 = __float2half(v.z), h3 = __float2half(v.w);
        uint2 ph;
        ph.x = (uint32_t)__half_as_ushort(h0) | ((uint32_t)__half_as_ushort(h1) << 16);
        ph.y = (uint32_t)__half_as_ushort(h2) | ((uint32_t)__half_as_ushort(h3) << 16);
        ((uint2*)g_h16)[(size_t)row * 64 + idx] = ph;
    }
    #pragma unroll
    for (int o = 16; o; o >>= 1) s += __shfl_xor_sync(0xffffffffu, s, o);
    if (lane == 0) g_sq[row] = s;
}

// ---------------------------------------------------------------------------
// loss_cl + loss_ce: one warp per row
// ---------------------------------------------------------------------------
__global__ void logit_kernel(const float* __restrict__ L, const int* __restrict__ y) {
    int warp = (blockIdx.x * blockDim.x + threadIdx.x) >> 5;
    int lane = threadIdx.x & 31;
    if (warp >= N_ALL) return;
    const float* row = L + (size_t)warp * C_CLS;

    float l0 = (lane < C_CLS) ? row[lane] : -3.4e38f;
    float l1 = (lane + 32 < C_CLS) ? row[lane + 32] : -3.4e38f;
    float l2 = (lane + 64 < C_CLS) ? row[lane + 64] : -3.4e38f;

    float m = fmaxf(l0, fmaxf(l1, l2));
    #pragma unroll
    for (int o = 16; o; o >>= 1) m = fmaxf(m, __shfl_xor_sync(0xffffffffu, m, o));

    float e0 = (lane < C_CLS) ? expf(l0 - m) : 0.f;
    float e1 = (lane + 32 < C_CLS) ? expf(l1 - m) : 0.f;
    float e2 = (lane + 64 < C_CLS) ? expf(l2 - m) : 0.f;
    float s = e0 + e1 + e2;
    #pragma unroll
    for (int o = 16; o; o >>= 1) s += __shfl_xor_sync(0xffffffffu, s, o);

    if (warp < S_SRC) {
        if (lane == 0) {
            float ly = row[y[warp]];
            g_row_cl[warp] = -(ly - m - logf(s));
        }
    } else {
        float inv = 1.f / s;
        float ent = 0.f;
        if (lane < C_CLS)      { float p = e0 * inv; ent -= p * log2f(fmaxf(p, 1e-8f)); }
        if (lane + 32 < C_CLS) { float p = e1 * inv; ent -= p * log2f(fmaxf(p, 1e-8f)); }
        if (lane + 64 < C_CLS) { float p = e2 * inv; ent -= p * log2f(fmaxf(p, 1e-8f)); }
        #pragma unroll
        for (int o = 16; o; o >>= 1) ent += __shfl_xor_sync(0xffffffffu, ent, o);
        if (lane == 0) g_row_ce[warp - S_SRC] = ent;
    }
}

// ---------------------------------------------------------------------------
__device__ __forceinline__ void ins5(float (&m)[5], float v) {
    if (v < m[4]) {
        if (v < m[3]) { m[4] = m[3];
            if (v < m[2]) { m[3] = m[2];
                if (v < m[1]) { m[2] = m[1];
                    if (v < m[0]) { m[1] = m[0]; m[0] = v; } else m[1] = v;
                } else m[2] = v;
            } else m[3] = v;
        } else m[4] = v;
    }
}

// Issue cp.async for one 128x256 fp16 tile (XOR-swizzled), rows [rbase, rbase+128)
__device__ __forceinline__ void load_tile(uint32_t dst_base, int rbase, int tid) {
    #pragma unroll
    for (int k = 0; k < 4; ++k) {
        int i = tid + k * NTHR;
        int row = i >> 5, u = i & 31;
        uint32_t sw = (uint32_t)(row * 512 + ((u ^ (row & 7)) << 4));
        CP_ASYNC16(dst_base + sw, (const char*)g_h16 + (size_t)(rbase + row) * 512 + (size_t)u * 16);
    }
}

// ---------------------------------------------------------------------------
// Persistent symmetric-tile HMMA Gram + dual-scan 5-min kernel.
// 148 CTAs x 1024 threads (32 warps: 4m x 8n, warp tile 32x16).
// Scans use per-q rotated order over a PADD=132 buffer: conflict-free LDS.
// ---------------------------------------------------------------------------
__global__ __launch_bounds__(NTHR, 1) void dist_mma_kernel() {
    extern __shared__ char dsm_raw[];
    uint32_t raw = smem_to_u32(dsm_raw);
    uint32_t sb = (raw + 1023u) & ~1023u;
    char* dsm = dsm_raw + (sb - raw);
    float* Dsm = (float*)(dsm + OFF_D);
    float* sqI = (float*)(dsm + OFF_SQI);
    float* sqJ = (float*)(dsm + OFF_SQJ);

    int tid = threadIdx.x;
    int lane = tid & 31, wid = tid >> 5;
    int wm = wid >> 3, wn = wid & 7;

    // chunk assignment: 2080 = 8*15 + 140*14
    int c = blockIdx.x;
    int ntile = 14 + (c < 8 ? 1 : 0);
    int t0 = c * 14 + (c < 8 ? c : 8);

    // decode first tile (I, J>=I)
    int I = 0, rem = t0;
    while (rem >= NT - I) { rem -= NT - I; ++I; }
    int J = I + rem;

    // constant ldmatrix pieces
    uint32_t a_base[2];
    #pragma unroll
    for (int mi = 0; mi < 2; ++mi)
        a_base[mi] = sb + OFF_A + (uint32_t)((wm * 32 + mi * 16 + (lane & 15)) * 512);
    uint32_t b_row_off = (uint32_t)((wn * 16 + (lane & 15)) * 512);
    int sxor = (lane & 15) & 7;
    int klane = lane >> 4;

    // initial load
    load_tile(sb + OFF_A, I * 128, tid);
    if (J != I) load_tile(sb + OFF_Bt, J * 128, tid);
    CP_COMMIT();

    for (int t = 0; t < ntile; ++t) {
        int rI = I * 128, rJ = J * 128;
        // sq loads are independent of cp.async — start them before the wait
        float sqv = 0.f;
        if (tid < 128) sqv = g_sq[rI + tid];
        else if (tid < 256) sqv = g_sq[rJ + tid - 128];
        CP_WAIT0();
        if (tid < 128) sqI[tid] = sqv;
        else if (tid < 256) sqJ[tid - 128] = sqv;
        __syncthreads();                 // tiles + sq visible

        uint32_t offB = (I == J) ? (uint32_t)OFF_A : (uint32_t)OFF_Bt;

        float acc[2][2][4];
        #pragma unroll
        for (int mi = 0; mi < 2; ++mi)
            #pragma unroll
            for (int ni = 0; ni < 2; ++ni)
                #pragma unroll
                for (int e = 0; e < 4; ++e) acc[mi][ni][e] = 0.f;

        // barrier-free k-loop: 16 chunks of k16 (3 LDSM + 4 MMA per warp)
        #pragma unroll 4
        for (int ks = 0; ks < 16; ++ks) {
            uint32_t au = (uint32_t)(((2 * ks + klane) ^ sxor) << 4);
            uint32_t ah[2][4], bh[4];
            LDSM4(ah[0], a_base[0] + au);
            LDSM4(ah[1], a_base[1] + au);
            LDSM4(bh, sb + offB + b_row_off + au);
            #pragma unroll
            for (int ni = 0; ni < 2; ++ni) {
                MMA16816(acc[0][ni], ah[0], bh[ni], bh[ni + 2]);
                MMA16816(acc[1][ni], ah[1], bh[ni], bh[ni + 2]);
            }
        }

        // stage raw dots to SMEM [row][col], pad 132, float2 stores
        #pragma unroll
        for (int mi = 0; mi < 2; ++mi)
            #pragma unroll
            for (int ni = 0; ni < 2; ++ni) {
                int row = wm * 32 + mi * 16 + (lane >> 2);
                int col = wn * 16 + ni * 8 + (lane & 3) * 2;
                *(float2*)&Dsm[row * PADD + col] = make_float2(acc[mi][ni][0], acc[mi][ni][1]);
                *(float2*)&Dsm[(row + 8) * PADD + col] = make_float2(acc[mi][ni][2], acc[mi][ni][3]);
            }
        __syncthreads();                 // Dsm ready; all warps done with A/B

        // prefetch next tile (overwrites A/B, now dead) — overlaps the scans
        int nI = I, nJ = J + 1;
        if (nJ == NT) { nI = I + 1; nJ = nI; }
        if (t + 1 < ntile) {
            if (nI != I) load_tile(sb + OFF_A, nI * 128, tid);
            if (nJ != nI) load_tile(sb + OFF_Bt, nJ * 128, tid);
        }
        CP_COMMIT();

        // dual scans, 4 threads per row/col (32 elems each), per-q rotated
        // order (bank-conflict-free); pair-merge via buffered shfl_xor
        if (tid < 512) {
            // row scan: row (rI + tid/4) vs cols of J
            int r = tid >> 2, q = tid & 3;
            float sqi = sqI[r];
            float s[5] = {3.4e38f, 3.4e38f, 3.4e38f, 3.4e38f, 3.4e38f};
            const float* drow = Dsm + r * PADD + q * 32;
            const float* sqc = sqJ + q * 32;
            #pragma unroll 4
            for (int i = 0; i < 32; ++i) {
                int cc = (i + q) & 31;
                ins5(s, fmaxf(fmaf(-2.f, drow[cc], sqi + sqc[cc]), 0.f));
            }
            #pragma unroll
            for (int off = 1; off <= 2; off <<= 1) {
                float tv[5];
                #pragma unroll
                for (int p = 0; p < 5; ++p) tv[p] = __shfl_xor_sync(0xffffffffu, s[p], off);
                #pragma unroll
                for (int p = 0; p < 5; ++p) ins5(s, tv[p]);
            }
            if (q == 0) {
                float* dst = g_part + ((size_t)(J >> 5) * N_ALL + rI + r) * 160 + (J & 31);
                #pragma unroll
                for (int p = 0; p < 5; ++p) dst[p * 32] = s[p];
            }
        } else if (I != J) {
            // col scan: row (rJ + cc) vs cols of I (transposed view)
            int cc = (tid - 512) >> 2, q = tid & 3;
            float sqj = sqJ[cc];
            float s[5] = {3.4e38f, 3.4e38f, 3.4e38f, 3.4e38f, 3.4e38f};
            #pragma unroll 4
            for (int i = 0; i < 32; ++i) {
                int rr = q * 32 + ((i + 2 * q) & 31);
                ins5(s, fmaxf(fmaf(-2.f, Dsm[rr * PADD + cc], sqj + sqI[rr]), 0.f));
            }
            #pragma unroll
            for (int off = 1; off <= 2; off <<= 1) {
                float tv[5];
                #pragma unroll
                for (int p = 0; p < 5; ++p) tv[p] = __shfl_xor_sync(0xffffffffu, s[p], off);
                #pragma unroll
                for (int p = 0; p < 5; ++p) ins5(s, tv[p]);
            }
            if (q == 0) {
                float* dst = g_part + ((size_t)(I >> 5) * N_ALL + rJ + cc) * 160 + (I & 31);
                #pragma unroll
                for (int p = 0; p < 5; ++p) dst[p * 32] = s[p];
            }
        }
        __syncthreads();                 // protect sq/Dsm before next iteration
        I = nI; J = nJ;
    }
}

// ---------------------------------------------------------------------------
// Merge 32 per-coltile partials per (half,row): one warp per row,
// lane = coltile (coalesced reads), 5x shfl_xor butterfly of sorted 5-lists.
// ---------------------------------------------------------------------------
__global__ void merge_kernel() {
    int gw = (blockIdx.x * blockDim.x + threadIdx.x) >> 5;   // 0..16383
    int lane = threadIdx.x & 31;
    if (gw >= 2 * N_ALL) return;
    const float* p = g_part + (size_t)gw * 160 + lane;
    float s[5];
    #pragma unroll
    for (int q = 0; q < 5; ++q) s[q] = p[q * 32];            // sorted ascending
    #pragma unroll
    for (int off = 16; off; off >>= 1) {
        float tv[5];
        #pragma unroll
        for (int q = 0; q < 5; ++q) tv[q] = __shfl_xor_sync(0xffffffffu, s[q], off);
        #pragma unroll
        for (int q = 0; q < 5; ++q) ins5(s, tv[q]);
    }
    if (lane == 0) {
        int h = gw >> 13, r = gw & (N_ALL - 1);
        // intra half: diag (~0, fp16 eps, clamped) occupies s[0];
        // dmin = s[1]; 5th smallest incl diag = s[4] (matches reference top_k)
        bool intra = ((r < S_SRC) == (h == 0));
        float dmin2 = intra ? s[1] : s[0];
        float kth2 = s[4];
        g_simh[h * N_ALL + r] = expf(-sqrtf(dmin2) / (2.f * (sqrtf(kth2) + 1e-8f)));
    }
}

// ---------------------------------------------------------------------------
// Deterministic final reduction: one block per output
// ---------------------------------------------------------------------------
__global__ void reduce_kernel(float* __restrict__ out) {
    __shared__ float sh[1024];
    int b = blockIdx.x, t = threadIdx.x;
    float a = 0.f;
    if (b == 0)      { for (int i = t; i < S_SRC; i += 1024) a += g_row_cl[i]; }
    else if (b == 1) { for (int i = t; i < S_SRC; i += 1024) a += g_row_ce[i]; }
    else             { for (int i = t; i < N_ALL; i += 1024) a += fabsf(g_simh[i] - g_simh[N_ALL + i]); }
    sh[t] = a; __syncthreads();
    for (int o = 512; o; o >>= 1) { if (t < o) sh[t] += sh[t + o]; __syncthreads(); }
    if (t == 0) out[b] = sh[0] / (float)S_SRC;
}

// ---------------------------------------------------------------------------
extern "C" void kernel_launch(void* const* d_in, const int* in_sizes, int n_in,
                              void* d_out, int out_size) {
    const float* F = (const float*)d_in[0];   // Feature_all [8192,256] f32
    const float* L = (const float*)d_in[1];   // logit_all   [8192,65]  f32
    const int*   y = (const int*)d_in[2];     // y_source    [4096]     i32
    float* out = (float*)d_out;

    cudaFuncSetAttribute(dist_mma_kernel, cudaFuncAttributeMaxDynamicSharedMemorySize, SMEM_ALLOC);

    prep_kernel<<<N_ALL / 16, 256>>>(F, 0);           // rows 0..4095
    prep_kernel<<<N_ALL / 16, 256>>>(F, N_ALL / 2);   // rows 4096..8191
    logit_kernel<<<N_ALL / 8, 256>>>(L, y);
    dist_mma_kernel<<<NCTA, NTHR, SMEM_ALLOC>>>();    // 4th launch -> ncu captures this
    merge_kernel<<<2 * N_ALL * 32 / 256, 256>>>();
    reduce_kernel<<<3, 1024>>>(out);
}